// round 1
// baseline (speedup 1.0000x reference)
#include <cuda_runtime.h>
#include <math_constants.h>

#define B_    2
#define S_    2048
#define NX_   1024
#define NST   1024
#define NH    16
#define HD    64
#define MROWS 4096
#define C3    3072

// Scratch (no allocations allowed)
__device__ float g_qkv[MROWS * C3];    // [4096, 3072]  (q|k|v)
__device__ float g_attn[MROWS * NST];  // [4096, 1024]  merged heads

// ---------------------------------------------------------------------------
// SGEMM: C[M,N] = A[M,K] @ B[K,N] + bias[N]
// 128x128 tile, BK=8, 256 threads, 8x8 per-thread microtile.
// M,N multiples of 128; K multiple of 8 (true for our shapes).
// ---------------------------------------------------------------------------
__global__ __launch_bounds__(256) void sgemm_bias_kernel(
    const float* __restrict__ A, const float* __restrict__ B,
    const float* __restrict__ bias, float* __restrict__ C,
    int M, int N, int K)
{
    __shared__ float As[8][128];
    __shared__ float Bs[8][128];

    const int tid = threadIdx.x;
    const int bm = blockIdx.y, bn = blockIdx.x;

    const int a_row = tid >> 1;            // 0..127
    const int a_col = (tid & 1) << 2;      // 0 or 4
    const int b_row = tid >> 5;            // 0..7
    const int b_col = (tid & 31) << 2;     // 0..124
    const int tx = tid & 15, ty = tid >> 4;

    const float* Aptr = A + (size_t)(bm * 128 + a_row) * K + a_col;
    const float* Bptr = B + (size_t)b_row * N + bn * 128 + b_col;

    float acc[8][8];
    #pragma unroll
    for (int i = 0; i < 8; i++)
        #pragma unroll
        for (int j = 0; j < 8; j++) acc[i][j] = 0.0f;

    for (int k0 = 0; k0 < K; k0 += 8) {
        float4 av = *(const float4*)(Aptr + k0);
        float4 bv = *(const float4*)(Bptr + (size_t)k0 * N);
        As[a_col + 0][a_row] = av.x;
        As[a_col + 1][a_row] = av.y;
        As[a_col + 2][a_row] = av.z;
        As[a_col + 3][a_row] = av.w;
        *(float4*)&Bs[b_row][b_col] = bv;
        __syncthreads();

        #pragma unroll
        for (int kk = 0; kk < 8; kk++) {
            float af[8], bf[8];
            *(float4*)&af[0] = *(const float4*)&As[kk][ty * 8];
            *(float4*)&af[4] = *(const float4*)&As[kk][ty * 8 + 4];
            *(float4*)&bf[0] = *(const float4*)&Bs[kk][tx * 8];
            *(float4*)&bf[4] = *(const float4*)&Bs[kk][tx * 8 + 4];
            #pragma unroll
            for (int i = 0; i < 8; i++)
                #pragma unroll
                for (int j = 0; j < 8; j++)
                    acc[i][j] = fmaf(af[i], bf[j], acc[i][j]);
        }
        __syncthreads();
    }

    const int colb = bn * 128 + tx * 8;
    #pragma unroll
    for (int i = 0; i < 8; i++) {
        const int row = bm * 128 + ty * 8 + i;
        float* Crow = C + (size_t)row * N + colb;
        float4 o0, o1;
        o0.x = acc[i][0] + bias[colb + 0];
        o0.y = acc[i][1] + bias[colb + 1];
        o0.z = acc[i][2] + bias[colb + 2];
        o0.w = acc[i][3] + bias[colb + 3];
        o1.x = acc[i][4] + bias[colb + 4];
        o1.y = acc[i][5] + bias[colb + 5];
        o1.z = acc[i][6] + bias[colb + 6];
        o1.w = acc[i][7] + bias[colb + 7];
        *(float4*)Crow       = o0;
        *(float4*)(Crow + 4) = o1;
    }
}

// ---------------------------------------------------------------------------
// Flash attention, fp32. BM=BN=64, D=64. Block = 256 threads (16x16), each
// thread owns a 4x4 microtile of scores / output. Online softmax with
// 16-lane shuffle reductions (threads sharing ty are contiguous lanes).
// qkv layout: row (b*S + s), cols [0,1024)=q, [1024,2048)=k, [2048,3072)=v,
// head h at col offset h*64 within each third.
// ---------------------------------------------------------------------------
#define PITCH 65
#define FLASH_SMEM (4 * 64 * PITCH * 4)

__global__ __launch_bounds__(256) void flash_kernel(
    const float* __restrict__ qkv, float* __restrict__ outp)
{
    extern __shared__ float sm[];
    float* Qs = sm;
    float* Ks = sm + 64 * PITCH;
    float* Vs = sm + 2 * 64 * PITCH;
    float* Ps = sm + 3 * 64 * PITCH;

    const int qb  = blockIdx.x;   // query tile 0..31
    const int h   = blockIdx.y;   // head 0..15
    const int b   = blockIdx.z;   // batch 0..1
    const int tid = threadIdx.x;
    const int tx = tid & 15, ty = tid >> 4;

    const float* base = qkv + (size_t)b * S_ * C3;
    const int hoff = h * HD;

    // Load Q tile, pre-scaled by rsqrt(64) = 0.125
    #pragma unroll
    for (int t = 0; t < 4; t++) {
        int fi = tid + t * 256;
        int r = fi >> 4, c4 = (fi & 15) << 2;
        float4 v = *(const float4*)(base + (size_t)(qb * 64 + r) * C3 + hoff + c4);
        Qs[r * PITCH + c4 + 0] = v.x * 0.125f;
        Qs[r * PITCH + c4 + 1] = v.y * 0.125f;
        Qs[r * PITCH + c4 + 2] = v.z * 0.125f;
        Qs[r * PITCH + c4 + 3] = v.w * 0.125f;
    }

    float m_prev[4], l_prev[4], acc[4][4];
    #pragma unroll
    for (int i = 0; i < 4; i++) {
        m_prev[i] = -CUDART_INF_F;
        l_prev[i] = 0.0f;
        #pragma unroll
        for (int j = 0; j < 4; j++) acc[i][j] = 0.0f;
    }

    for (int j = 0; j <= qb; j++) {
        // Load K and V tiles
        #pragma unroll
        for (int t = 0; t < 4; t++) {
            int fi = tid + t * 256;
            int r = fi >> 4, c4 = (fi & 15) << 2;
            const float* kp = base + (size_t)(j * 64 + r) * C3 + NST + hoff + c4;
            float4 kv = *(const float4*)kp;
            float4 vv = *(const float4*)(kp + NST);
            Ks[r * PITCH + c4 + 0] = kv.x;
            Ks[r * PITCH + c4 + 1] = kv.y;
            Ks[r * PITCH + c4 + 2] = kv.z;
            Ks[r * PITCH + c4 + 3] = kv.w;
            Vs[r * PITCH + c4 + 0] = vv.x;
            Vs[r * PITCH + c4 + 1] = vv.y;
            Vs[r * PITCH + c4 + 2] = vv.z;
            Vs[r * PITCH + c4 + 3] = vv.w;
        }
        __syncthreads();

        // S = Q K^T (already scaled)
        float s[4][4];
        #pragma unroll
        for (int i = 0; i < 4; i++)
            #pragma unroll
            for (int jj = 0; jj < 4; jj++) s[i][jj] = 0.0f;

        #pragma unroll 16
        for (int kk = 0; kk < 64; kk++) {
            float qv[4], kv[4];
            #pragma unroll
            for (int i = 0; i < 4; i++)  qv[i]  = Qs[(ty * 4 + i) * PITCH + kk];
            #pragma unroll
            for (int jj = 0; jj < 4; jj++) kv[jj] = Ks[(tx * 4 + jj) * PITCH + kk];
            #pragma unroll
            for (int i = 0; i < 4; i++)
                #pragma unroll
                for (int jj = 0; jj < 4; jj++)
                    s[i][jj] = fmaf(qv[i], kv[jj], s[i][jj]);
        }

        // Causal mask on the diagonal tile
        if (j == qb) {
            #pragma unroll
            for (int i = 0; i < 4; i++)
                #pragma unroll
                for (int jj = 0; jj < 4; jj++)
                    if (tx * 4 + jj > ty * 4 + i) s[i][jj] = -1e30f;
        }

        // Online softmax, per owned row (reduce over the 16 tx lanes)
        #pragma unroll
        for (int i = 0; i < 4; i++) {
            float mt = fmaxf(fmaxf(s[i][0], s[i][1]), fmaxf(s[i][2], s[i][3]));
            mt = fmaxf(mt, __shfl_xor_sync(0xffffffffu, mt, 1));
            mt = fmaxf(mt, __shfl_xor_sync(0xffffffffu, mt, 2));
            mt = fmaxf(mt, __shfl_xor_sync(0xffffffffu, mt, 4));
            mt = fmaxf(mt, __shfl_xor_sync(0xffffffffu, mt, 8));
            float m_new = fmaxf(m_prev[i], mt);
            float ssum = 0.0f;
            #pragma unroll
            for (int jj = 0; jj < 4; jj++) {
                s[i][jj] = __expf(s[i][jj] - m_new);
                ssum += s[i][jj];
            }
            ssum += __shfl_xor_sync(0xffffffffu, ssum, 1);
            ssum += __shfl_xor_sync(0xffffffffu, ssum, 2);
            ssum += __shfl_xor_sync(0xffffffffu, ssum, 4);
            ssum += __shfl_xor_sync(0xffffffffu, ssum, 8);
            float alpha = __expf(m_prev[i] - m_new);
            l_prev[i] = l_prev[i] * alpha + ssum;
            m_prev[i] = m_new;
            #pragma unroll
            for (int jj = 0; jj < 4; jj++) acc[i][jj] *= alpha;
        }

        // Stage P to smem for the PV gemm
        #pragma unroll
        for (int i = 0; i < 4; i++)
            #pragma unroll
            for (int jj = 0; jj < 4; jj++)
                Ps[(ty * 4 + i) * PITCH + tx * 4 + jj] = s[i][jj];
        __syncthreads();

        // O += P V
        #pragma unroll 16
        for (int kk = 0; kk < 64; kk++) {
            float pv[4], vv[4];
            #pragma unroll
            for (int i = 0; i < 4; i++)  pv[i]  = Ps[(ty * 4 + i) * PITCH + kk];
            #pragma unroll
            for (int jj = 0; jj < 4; jj++) vv[jj] = Vs[kk * PITCH + tx * 4 + jj];
            #pragma unroll
            for (int i = 0; i < 4; i++)
                #pragma unroll
                for (int jj = 0; jj < 4; jj++)
                    acc[i][jj] = fmaf(pv[i], vv[jj], acc[i][jj]);
        }
        __syncthreads();
    }

    // Normalize and write merged-head output
    #pragma unroll
    for (int i = 0; i < 4; i++) {
        const int r = qb * 64 + ty * 4 + i;
        const float inv = 1.0f / l_prev[i];
        float* op = outp + ((size_t)b * S_ + r) * NST + hoff + tx * 4;
        #pragma unroll
        for (int jj = 0; jj < 4; jj++) op[jj] = acc[i][jj] * inv;
    }
}

// ---------------------------------------------------------------------------
extern "C" void kernel_launch(void* const* d_in, const int* in_sizes, int n_in,
                              void* d_out, int out_size)
{
    const float* x   = (const float*)d_in[0];
    const float* w_c = (const float*)d_in[1];
    const float* b_c = (const float*)d_in[2];
    const float* w_p = (const float*)d_in[3];
    const float* b_p = (const float*)d_in[4];
    float* out = (float*)d_out;

    void *qkv_p = nullptr, *attn_p = nullptr;
    cudaGetSymbolAddress(&qkv_p, g_qkv);
    cudaGetSymbolAddress(&attn_p, g_attn);
    float* qkv  = (float*)qkv_p;
    float* attn = (float*)attn_p;

    // 1) QKV projection: [4096,1024] @ [1024,3072] + b_c
    sgemm_bias_kernel<<<dim3(C3 / 128, MROWS / 128), 256>>>(
        x, w_c, b_c, qkv, MROWS, C3, NX_);

    // 2) Flash attention per (qb, head, batch)
    cudaFuncSetAttribute(flash_kernel,
                         cudaFuncAttributeMaxDynamicSharedMemorySize, FLASH_SMEM);
    flash_kernel<<<dim3(S_ / 64, NH, B_), 256, FLASH_SMEM>>>(qkv, attn);

    // 3) Output projection: [4096,1024] @ [1024,1024] + b_p
    sgemm_bias_kernel<<<dim3(NST / 128, MROWS / 128), 256>>>(
        attn, w_p, b_p, out, MROWS, NST, NX_);
}

// round 4
// speedup vs baseline: 1.4219x; 1.4219x over previous
#include <cuda_runtime.h>
#include <math_constants.h>
#include <cstdint>

#define B_    2
#define S_    2048
#define NX_   1024
#define NST   1024
#define NH    16
#define HD    64
#define MROWS 4096
#define C3    3072

// Scratch (no allocations allowed)
__device__ float g_qkv[MROWS * C3];    // [4096, 3072]  (q|k|v)
__device__ float g_attn[MROWS * NST];  // [4096, 1024]  merged heads (tf32-rounded)
__device__ float g_xr[MROWS * NX_];    // x, tf32-rounded
__device__ float g_wct[C3 * NX_];      // w_c transposed [3072,1024], tf32-rounded
__device__ float g_wpt[NST * NX_];     // w_p transposed [1024,1024], tf32-rounded

__device__ __forceinline__ float cvt_tf32(float x) {
    float y;
    asm("cvt.rna.tf32.f32 %0, %1;" : "=f"(y) : "f"(x));
    return y;
}
__device__ __forceinline__ uint32_t smem_u32(const void* p) {
    uint32_t a;
    asm("{ .reg .u64 t; cvta.to.shared.u64 t, %1; cvt.u32.u64 %0, t; }"
        : "=r"(a) : "l"(p));
    return a;
}
#define CP_ASYNC16(smaddr, gptr) \
    asm volatile("cp.async.cg.shared.global [%0], [%1], 16;" \
                 :: "r"(smaddr), "l"(gptr) : "memory")
#define CP_COMMIT() asm volatile("cp.async.commit_group;" ::: "memory")
#define CP_WAIT2()  asm volatile("cp.async.wait_group 2;" ::: "memory")

// ---------------------------------------------------------------------------
// Elementwise tf32 rounding (for GEMM A operands fed via cp.async)
// ---------------------------------------------------------------------------
__global__ __launch_bounds__(256) void round_tf32_kernel(
    const float* __restrict__ in, float* __restrict__ out, int n4)
{
    int i = blockIdx.x * 256 + threadIdx.x;
    if (i < n4) {
        float4 v = ((const float4*)in)[i];
        v.x = cvt_tf32(v.x); v.y = cvt_tf32(v.y);
        v.z = cvt_tf32(v.z); v.w = cvt_tf32(v.w);
        ((float4*)out)[i] = v;
    }
}

// ---------------------------------------------------------------------------
// Transpose + tf32 round:  WT[n*K + k] = tf32(W[k*N + n])
// ---------------------------------------------------------------------------
__global__ __launch_bounds__(256) void transpose_round_kernel(
    const float* __restrict__ W, float* __restrict__ WT, int K, int N)
{
    __shared__ float t[32][33];
    const int tx = threadIdx.x, ty = threadIdx.y;
    const int n0 = blockIdx.x * 32, k0 = blockIdx.y * 32;
    #pragma unroll
    for (int i = 0; i < 32; i += 8)
        t[ty + i][tx] = W[(size_t)(k0 + ty + i) * N + n0 + tx];
    __syncthreads();
    #pragma unroll
    for (int i = 0; i < 32; i += 8)
        WT[(size_t)(n0 + ty + i) * K + k0 + tx] = cvt_tf32(t[tx][ty + i]);
}

// ---------------------------------------------------------------------------
// tf32 mma.sync GEMM:  C[M,N] = A[M,K] @ BT[N,K]^T + bias
// BM=128, BN=128, BK=16. 256 threads = 8 warps (2 x 4), 64x32 per warp.
// A and BT must be tf32-pre-rounded. 3-stage cp.async pipeline.
// Smem tiles stored [row][k] with pitch 20 floats (80 B: 16B-aligned rows,
// conflict-free quad access: banks (20*gid+tig) mod 32 all distinct).
// ---------------------------------------------------------------------------
#define GBM 128
#define GBN 128
#define GBK 16
#define TPITCH 20
#define TILE_F (128 * TPITCH)            // floats per tile per stage
#define GEMM_SMEM (6 * TILE_F * 4)       // 3 stages x (A + B) = 61440 B

__global__ __launch_bounds__(256) void gemm_mma_kernel(
    const float* __restrict__ A, const float* __restrict__ BT,
    const float* __restrict__ bias, float* __restrict__ C,
    int M, int N, int K)
{
    extern __shared__ __align__(16) float smf[];
    const uint32_t smb = smem_u32(smf);

    const int tid = threadIdx.x;
    const int wid = tid >> 5, lane = tid & 31;
    const int gid = lane >> 2, tig = lane & 3;
    const int warp_m = wid & 1, warp_n = wid >> 1;

    const int m0 = blockIdx.y * GBM;
    const int n0 = blockIdx.x * GBN;

    // cp.async mapping: per tile, each thread copies 2 float4
    const int cr = tid >> 1;                  // row 0..127
    const int cc0 = (tid & 1) << 2;           // k-col 0 or 4
    const int cc1 = cc0 + 8;                  // k-col 8 or 12

    const float* Ap = A + (size_t)m0 * K;
    const float* Bp = BT + (size_t)n0 * K;

    const int nchunk = K / GBK;

    float acc[4][4][4];
    #pragma unroll
    for (int i = 0; i < 4; i++)
        #pragma unroll
        for (int j = 0; j < 4; j++)
            #pragma unroll
            for (int r = 0; r < 4; r++) acc[i][j][r] = 0.0f;

    #define PREFETCH(kc, st) do {                                               \
        const uint32_t abase = smb + (st) * TILE_F * 4;                         \
        const uint32_t bbase = smb + (3 + (st)) * TILE_F * 4;                   \
        CP_ASYNC16(abase + (cr * TPITCH + cc0) * 4,                             \
                   Ap + (size_t)cr * K + (kc) * GBK + cc0);                     \
        CP_ASYNC16(abase + (cr * TPITCH + cc1) * 4,                             \
                   Ap + (size_t)cr * K + (kc) * GBK + cc1);                     \
        CP_ASYNC16(bbase + (cr * TPITCH + cc0) * 4,                             \
                   Bp + (size_t)cr * K + (kc) * GBK + cc0);                     \
        CP_ASYNC16(bbase + (cr * TPITCH + cc1) * 4,                             \
                   Bp + (size_t)cr * K + (kc) * GBK + cc1);                     \
    } while (0)

    PREFETCH(0, 0); CP_COMMIT();
    PREFETCH(1, 1); CP_COMMIT();

    for (int kc = 0; kc < nchunk; kc++) {
        const int st = kc % 3;
        __syncthreads();                       // all warps done with stage (kc+2)%3
        if (kc + 2 < nchunk) { PREFETCH(kc + 2, (kc + 2) % 3); }
        CP_COMMIT();
        CP_WAIT2();                            // stage kc data arrived
        __syncthreads();

        const float* As = smf + st * TILE_F;
        const float* Bs = smf + (3 + st) * TILE_F;

        #pragma unroll
        for (int k0 = 0; k0 < 16; k0 += 8) {
            uint32_t afr[4][4], bfr[4][2];
            #pragma unroll
            for (int i = 0; i < 4; i++) {
                const int mr = warp_m * 64 + i * 16 + gid;
                afr[i][0] = __float_as_uint(As[mr * TPITCH + k0 + tig]);
                afr[i][1] = __float_as_uint(As[(mr + 8) * TPITCH + k0 + tig]);
                afr[i][2] = __float_as_uint(As[mr * TPITCH + k0 + tig + 4]);
                afr[i][3] = __float_as_uint(As[(mr + 8) * TPITCH + k0 + tig + 4]);
            }
            #pragma unroll
            for (int j = 0; j < 4; j++) {
                const int nc = warp_n * 32 + j * 8 + gid;
                bfr[j][0] = __float_as_uint(Bs[nc * TPITCH + k0 + tig]);
                bfr[j][1] = __float_as_uint(Bs[nc * TPITCH + k0 + tig + 4]);
            }
            #pragma unroll
            for (int i = 0; i < 4; i++)
                #pragma unroll
                for (int j = 0; j < 4; j++) {
                    asm volatile(
                        "mma.sync.aligned.m16n8k8.row.col.f32.tf32.tf32.f32 "
                        "{%0,%1,%2,%3}, {%4,%5,%6,%7}, {%8,%9}, {%0,%1,%2,%3};"
                        : "+f"(acc[i][j][0]), "+f"(acc[i][j][1]),
                          "+f"(acc[i][j][2]), "+f"(acc[i][j][3])
                        : "r"(afr[i][0]), "r"(afr[i][1]),
                          "r"(afr[i][2]), "r"(afr[i][3]),
                          "r"(bfr[j][0]), "r"(bfr[j][1]));
                }
        }
    }

    // Epilogue: write with bias
    #pragma unroll
    for (int i = 0; i < 4; i++) {
        const int r0 = m0 + warp_m * 64 + i * 16 + gid;
        #pragma unroll
        for (int j = 0; j < 4; j++) {
            const int col = n0 + warp_n * 32 + j * 8 + 2 * tig;
            const float bx = bias[col], by = bias[col + 1];
            float2 v0 = make_float2(acc[i][j][0] + bx, acc[i][j][1] + by);
            float2 v1 = make_float2(acc[i][j][2] + bx, acc[i][j][3] + by);
            *(float2*)(C + (size_t)r0 * N + col) = v0;
            *(float2*)(C + (size_t)(r0 + 8) * N + col) = v1;
        }
    }
}

// ---------------------------------------------------------------------------
// Flash attention, fp32. Output rounded to tf32 (feeds proj GEMM).
// ---------------------------------------------------------------------------
#define PITCH 65
#define FLASH_SMEM (4 * 64 * PITCH * 4)

__global__ __launch_bounds__(256) void flash_kernel(
    const float* __restrict__ qkv, float* __restrict__ outp)
{
    extern __shared__ float sm[];
    float* Qs = sm;
    float* Ks = sm + 64 * PITCH;
    float* Vs = sm + 2 * 64 * PITCH;
    float* Ps = sm + 3 * 64 * PITCH;

    const int qb  = blockIdx.x;
    const int h   = blockIdx.y;
    const int b   = blockIdx.z;
    const int tid = threadIdx.x;
    const int tx = tid & 15, ty = tid >> 4;

    const float* base = qkv + (size_t)b * S_ * C3;
    const int hoff = h * HD;

    #pragma unroll
    for (int t = 0; t < 4; t++) {
        int fi = tid + t * 256;
        int r = fi >> 4, c4 = (fi & 15) << 2;
        float4 v = *(const float4*)(base + (size_t)(qb * 64 + r) * C3 + hoff + c4);
        Qs[r * PITCH + c4 + 0] = v.x * 0.125f;
        Qs[r * PITCH + c4 + 1] = v.y * 0.125f;
        Qs[r * PITCH + c4 + 2] = v.z * 0.125f;
        Qs[r * PITCH + c4 + 3] = v.w * 0.125f;
    }

    float m_prev[4], l_prev[4], acc[4][4];
    #pragma unroll
    for (int i = 0; i < 4; i++) {
        m_prev[i] = -CUDART_INF_F;
        l_prev[i] = 0.0f;
        #pragma unroll
        for (int j = 0; j < 4; j++) acc[i][j] = 0.0f;
    }

    for (int j = 0; j <= qb; j++) {
        #pragma unroll
        for (int t = 0; t < 4; t++) {
            int fi = tid + t * 256;
            int r = fi >> 4, c4 = (fi & 15) << 2;
            const float* kp = base + (size_t)(j * 64 + r) * C3 + NST + hoff + c4;
            float4 kv = *(const float4*)kp;
            float4 vv = *(const float4*)(kp + NST);
            Ks[r * PITCH + c4 + 0] = kv.x;
            Ks[r * PITCH + c4 + 1] = kv.y;
            Ks[r * PITCH + c4 + 2] = kv.z;
            Ks[r * PITCH + c4 + 3] = kv.w;
            Vs[r * PITCH + c4 + 0] = vv.x;
            Vs[r * PITCH + c4 + 1] = vv.y;
            Vs[r * PITCH + c4 + 2] = vv.z;
            Vs[r * PITCH + c4 + 3] = vv.w;
        }
        __syncthreads();

        float s[4][4];
        #pragma unroll
        for (int i = 0; i < 4; i++)
            #pragma unroll
            for (int jj = 0; jj < 4; jj++) s[i][jj] = 0.0f;

        #pragma unroll 16
        for (int kk = 0; kk < 64; kk++) {
            float qv[4], kv[4];
            #pragma unroll
            for (int i = 0; i < 4; i++)  qv[i]  = Qs[(ty * 4 + i) * PITCH + kk];
            #pragma unroll
            for (int jj = 0; jj < 4; jj++) kv[jj] = Ks[(tx * 4 + jj) * PITCH + kk];
            #pragma unroll
            for (int i = 0; i < 4; i++)
                #pragma unroll
                for (int jj = 0; jj < 4; jj++)
                    s[i][jj] = fmaf(qv[i], kv[jj], s[i][jj]);
        }

        if (j == qb) {
            #pragma unroll
            for (int i = 0; i < 4; i++)
                #pragma unroll
                for (int jj = 0; jj < 4; jj++)
                    if (tx * 4 + jj > ty * 4 + i) s[i][jj] = -1e30f;
        }

        #pragma unroll
        for (int i = 0; i < 4; i++) {
            float mt = fmaxf(fmaxf(s[i][0], s[i][1]), fmaxf(s[i][2], s[i][3]));
            mt = fmaxf(mt, __shfl_xor_sync(0xffffffffu, mt, 1));
            mt = fmaxf(mt, __shfl_xor_sync(0xffffffffu, mt, 2));
            mt = fmaxf(mt, __shfl_xor_sync(0xffffffffu, mt, 4));
            mt = fmaxf(mt, __shfl_xor_sync(0xffffffffu, mt, 8));
            float m_new = fmaxf(m_prev[i], mt);
            float ssum = 0.0f;
            #pragma unroll
            for (int jj = 0; jj < 4; jj++) {
                s[i][jj] = __expf(s[i][jj] - m_new);
                ssum += s[i][jj];
            }
            ssum += __shfl_xor_sync(0xffffffffu, ssum, 1);
            ssum += __shfl_xor_sync(0xffffffffu, ssum, 2);
            ssum += __shfl_xor_sync(0xffffffffu, ssum, 4);
            ssum += __shfl_xor_sync(0xffffffffu, ssum, 8);
            float alpha = __expf(m_prev[i] - m_new);
            l_prev[i] = l_prev[i] * alpha + ssum;
            m_prev[i] = m_new;
            #pragma unroll
            for (int jj = 0; jj < 4; jj++) acc[i][jj] *= alpha;
        }

        #pragma unroll
        for (int i = 0; i < 4; i++)
            #pragma unroll
            for (int jj = 0; jj < 4; jj++)
                Ps[(ty * 4 + i) * PITCH + tx * 4 + jj] = s[i][jj];
        __syncthreads();

        #pragma unroll 16
        for (int kk = 0; kk < 64; kk++) {
            float pv[4], vv[4];
            #pragma unroll
            for (int i = 0; i < 4; i++)  pv[i]  = Ps[(ty * 4 + i) * PITCH + kk];
            #pragma unroll
            for (int jj = 0; jj < 4; jj++) vv[jj] = Vs[kk * PITCH + tx * 4 + jj];
            #pragma unroll
            for (int i = 0; i < 4; i++)
                #pragma unroll
                for (int jj = 0; jj < 4; jj++)
                    acc[i][jj] = fmaf(pv[i], vv[jj], acc[i][jj]);
        }
        __syncthreads();
    }

    #pragma unroll
    for (int i = 0; i < 4; i++) {
        const int r = qb * 64 + ty * 4 + i;
        const float inv = 1.0f / l_prev[i];
        float* op = outp + ((size_t)b * S_ + r) * NST + hoff + tx * 4;
        #pragma unroll
        for (int jj = 0; jj < 4; jj++) op[jj] = cvt_tf32(acc[i][jj] * inv);
    }
}

// ---------------------------------------------------------------------------
extern "C" void kernel_launch(void* const* d_in, const int* in_sizes, int n_in,
                              void* d_out, int out_size)
{
    const float* x   = (const float*)d_in[0];
    const float* w_c = (const float*)d_in[1];
    const float* b_c = (const float*)d_in[2];
    const float* w_p = (const float*)d_in[3];
    const float* b_p = (const float*)d_in[4];
    float* out = (float*)d_out;

    void *qkv_p, *attn_p, *xr_p, *wct_p, *wpt_p;
    cudaGetSymbolAddress(&qkv_p, g_qkv);
    cudaGetSymbolAddress(&attn_p, g_attn);
    cudaGetSymbolAddress(&xr_p, g_xr);
    cudaGetSymbolAddress(&wct_p, g_wct);
    cudaGetSymbolAddress(&wpt_p, g_wpt);
    float* qkv  = (float*)qkv_p;
    float* attn = (float*)attn_p;
    float* xr   = (float*)xr_p;
    float* wct  = (float*)wct_p;
    float* wpt  = (float*)wpt_p;

    static bool attr_done = false;
    if (!attr_done) {
        cudaFuncSetAttribute(gemm_mma_kernel,
                             cudaFuncAttributeMaxDynamicSharedMemorySize, GEMM_SMEM);
        cudaFuncSetAttribute(flash_kernel,
                             cudaFuncAttributeMaxDynamicSharedMemorySize, FLASH_SMEM);
        attr_done = true;
    }

    // 0) tf32-round x; transpose + round weights
    round_tf32_kernel<<<(MROWS * NX_ / 4 + 255) / 256, 256>>>(x, xr, MROWS * NX_ / 4);
    transpose_round_kernel<<<dim3(C3 / 32, NX_ / 32), dim3(32, 8)>>>(w_c, wct, NX_, C3);
    transpose_round_kernel<<<dim3(NST / 32, NX_ / 32), dim3(32, 8)>>>(w_p, wpt, NX_, NST);

    // 1) QKV projection (tensor cores, tf32)
    gemm_mma_kernel<<<dim3(C3 / GBN, MROWS / GBM), 256, GEMM_SMEM>>>(
        xr, wct, b_c, qkv, MROWS, C3, NX_);

    // 2) Flash attention (fp32, writes tf32-rounded attn)
    flash_kernel<<<dim3(S_ / 64, NH, B_), 256, FLASH_SMEM>>>(qkv, attn);

    // 3) Output projection (tensor cores, tf32)
    gemm_mma_kernel<<<dim3(NST / GBN, MROWS / GBM), 256, GEMM_SMEM>>>(
        attn, wpt, b_p, out, MROWS, NST, NX_);
}

// round 5
// speedup vs baseline: 2.5755x; 1.8112x over previous
#include <cuda_runtime.h>
#include <math_constants.h>
#include <cstdint>

#define B_    2
#define S_    2048
#define NX_   1024
#define NST   1024
#define NH    16
#define HD    64
#define MROWS 4096
#define C3    3072

// Scratch (no allocations allowed)
__device__ float g_qkv[MROWS * C3];    // [4096, 3072]  (q|k|v)
__device__ float g_attn[MROWS * NST];  // [4096, 1024]  merged heads (tf32-rounded)
__device__ float g_xr[MROWS * NX_];    // x, tf32-rounded
__device__ float g_wct[C3 * NX_];      // w_c transposed [3072,1024], tf32-rounded
__device__ float g_wpt[NST * NX_];     // w_p transposed [1024,1024], tf32-rounded

__device__ __forceinline__ float cvt_tf32(float x) {
    float y;
    asm("cvt.rna.tf32.f32 %0, %1;" : "=f"(y) : "f"(x));
    return y;
}
__device__ __forceinline__ uint32_t smem_u32(const void* p) {
    uint32_t a;
    asm("{ .reg .u64 t; cvta.to.shared.u64 t, %1; cvt.u32.u64 %0, t; }"
        : "=r"(a) : "l"(p));
    return a;
}
#define CP_ASYNC16(smaddr, gptr) \
    asm volatile("cp.async.cg.shared.global [%0], [%1], 16;" \
                 :: "r"(smaddr), "l"(gptr) : "memory")
#define CP_COMMIT() asm volatile("cp.async.commit_group;" ::: "memory")
#define CP_WAIT2()  asm volatile("cp.async.wait_group 2;" ::: "memory")

#define MMA_TF32(acc, a, b)                                                    \
    asm volatile(                                                              \
        "mma.sync.aligned.m16n8k8.row.col.f32.tf32.tf32.f32 "                  \
        "{%0,%1,%2,%3}, {%4,%5,%6,%7}, {%8,%9}, {%0,%1,%2,%3};"                \
        : "+f"((acc)[0]), "+f"((acc)[1]), "+f"((acc)[2]), "+f"((acc)[3])       \
        : "r"((a)[0]), "r"((a)[1]), "r"((a)[2]), "r"((a)[3]),                  \
          "r"((b)[0]), "r"((b)[1]))

// ---------------------------------------------------------------------------
// Elementwise tf32 rounding
// ---------------------------------------------------------------------------
__global__ __launch_bounds__(256) void round_tf32_kernel(
    const float* __restrict__ in, float* __restrict__ out, int n4)
{
    int i = blockIdx.x * 256 + threadIdx.x;
    if (i < n4) {
        float4 v = ((const float4*)in)[i];
        v.x = cvt_tf32(v.x); v.y = cvt_tf32(v.y);
        v.z = cvt_tf32(v.z); v.w = cvt_tf32(v.w);
        ((float4*)out)[i] = v;
    }
}

// ---------------------------------------------------------------------------
// Transpose + tf32 round:  WT[n*K + k] = tf32(W[k*N + n])
// ---------------------------------------------------------------------------
__global__ __launch_bounds__(256) void transpose_round_kernel(
    const float* __restrict__ W, float* __restrict__ WT, int K, int N)
{
    __shared__ float t[32][33];
    const int tx = threadIdx.x, ty = threadIdx.y;
    const int n0 = blockIdx.x * 32, k0 = blockIdx.y * 32;
    #pragma unroll
    for (int i = 0; i < 32; i += 8)
        t[ty + i][tx] = W[(size_t)(k0 + ty + i) * N + n0 + tx];
    __syncthreads();
    #pragma unroll
    for (int i = 0; i < 32; i += 8)
        WT[(size_t)(n0 + ty + i) * K + k0 + tx] = cvt_tf32(t[tx][ty + i]);
}

// ---------------------------------------------------------------------------
// tf32 mma.sync GEMM (unchanged from R4 — 272us QKV, tensor=31%)
// ---------------------------------------------------------------------------
#define GBM 128
#define GBN 128
#define GBK 16
#define TPITCH 20
#define TILE_F (128 * TPITCH)
#define GEMM_SMEM (6 * TILE_F * 4)

__global__ __launch_bounds__(256) void gemm_mma_kernel(
    const float* __restrict__ A, const float* __restrict__ BT,
    const float* __restrict__ bias, float* __restrict__ C,
    int M, int N, int K)
{
    extern __shared__ __align__(16) float smf[];
    const uint32_t smb = smem_u32(smf);

    const int tid = threadIdx.x;
    const int wid = tid >> 5, lane = tid & 31;
    const int gid = lane >> 2, tig = lane & 3;
    const int warp_m = wid & 1, warp_n = wid >> 1;

    const int m0 = blockIdx.y * GBM;
    const int n0 = blockIdx.x * GBN;

    const int cr = tid >> 1;
    const int cc0 = (tid & 1) << 2;
    const int cc1 = cc0 + 8;

    const float* Ap = A + (size_t)m0 * K;
    const float* Bp = BT + (size_t)n0 * K;

    const int nchunk = K / GBK;

    float acc[4][4][4];
    #pragma unroll
    for (int i = 0; i < 4; i++)
        #pragma unroll
        for (int j = 0; j < 4; j++)
            #pragma unroll
            for (int r = 0; r < 4; r++) acc[i][j][r] = 0.0f;

    #define PREFETCH(kc, st) do {                                               \
        const uint32_t abase = smb + (st) * TILE_F * 4;                         \
        const uint32_t bbase = smb + (3 + (st)) * TILE_F * 4;                   \
        CP_ASYNC16(abase + (cr * TPITCH + cc0) * 4,                             \
                   Ap + (size_t)cr * K + (kc) * GBK + cc0);                     \
        CP_ASYNC16(abase + (cr * TPITCH + cc1) * 4,                             \
                   Ap + (size_t)cr * K + (kc) * GBK + cc1);                     \
        CP_ASYNC16(bbase + (cr * TPITCH + cc0) * 4,                             \
                   Bp + (size_t)cr * K + (kc) * GBK + cc0);                     \
        CP_ASYNC16(bbase + (cr * TPITCH + cc1) * 4,                             \
                   Bp + (size_t)cr * K + (kc) * GBK + cc1);                     \
    } while (0)

    PREFETCH(0, 0); CP_COMMIT();
    PREFETCH(1, 1); CP_COMMIT();

    for (int kc = 0; kc < nchunk; kc++) {
        const int st = kc % 3;
        __syncthreads();
        if (kc + 2 < nchunk) { PREFETCH(kc + 2, (kc + 2) % 3); }
        CP_COMMIT();
        CP_WAIT2();
        __syncthreads();

        const float* As = smf + st * TILE_F;
        const float* Bs = smf + (3 + st) * TILE_F;

        #pragma unroll
        for (int k0 = 0; k0 < 16; k0 += 8) {
            uint32_t afr[4][4], bfr[4][2];
            #pragma unroll
            for (int i = 0; i < 4; i++) {
                const int mr = warp_m * 64 + i * 16 + gid;
                afr[i][0] = __float_as_uint(As[mr * TPITCH + k0 + tig]);
                afr[i][1] = __float_as_uint(As[(mr + 8) * TPITCH + k0 + tig]);
                afr[i][2] = __float_as_uint(As[mr * TPITCH + k0 + tig + 4]);
                afr[i][3] = __float_as_uint(As[(mr + 8) * TPITCH + k0 + tig + 4]);
            }
            #pragma unroll
            for (int j = 0; j < 4; j++) {
                const int nc = warp_n * 32 + j * 8 + gid;
                bfr[j][0] = __float_as_uint(Bs[nc * TPITCH + k0 + tig]);
                bfr[j][1] = __float_as_uint(Bs[nc * TPITCH + k0 + tig + 4]);
            }
            #pragma unroll
            for (int i = 0; i < 4; i++)
                #pragma unroll
                for (int j = 0; j < 4; j++)
                    MMA_TF32(acc[i][j], afr[i], bfr[j]);
        }
    }

    #pragma unroll
    for (int i = 0; i < 4; i++) {
        const int r0 = m0 + warp_m * 64 + i * 16 + gid;
        #pragma unroll
        for (int j = 0; j < 4; j++) {
            const int col = n0 + warp_n * 32 + j * 8 + 2 * tig;
            const float bx = bias[col], by = bias[col + 1];
            float2 v0 = make_float2(acc[i][j][0] + bx, acc[i][j][1] + by);
            float2 v1 = make_float2(acc[i][j][2] + bx, acc[i][j][3] + by);
            *(float2*)(C + (size_t)r0 * N + col) = v0;
            *(float2*)(C + (size_t)(r0 + 8) * N + col) = v1;
        }
    }
}

// ---------------------------------------------------------------------------
// Tensor-core flash attention (tf32 mma.sync).
// CTA = 128 q-rows for one (head, batch). 8 warps; warp w owns rows
// [w*16, w*16+16). Key tiles of 64. Q/K/P in pitch-68 smem (banks 4*gid+tig,
// conflict-free); V in pitch-72 (banks 8*tig+gid, conflict-free).
// Q pre-scaled by 0.125*log2(e) so softmax uses exp2f.
// Writes tf32-rounded merged-head output (feeds proj GEMM).
// ---------------------------------------------------------------------------
#define FP  68
#define FPV 72
#define QS_OFF 0
#define KS_OFF (128 * FP)
#define PS_OFF (192 * FP)
#define VS_OFF (320 * FP)
#define FLASH_SMEM ((320 * FP + 64 * FPV) * 4)   // 105472 B

__global__ __launch_bounds__(256) void flash_mma_kernel(
    const float* __restrict__ qkv, float* __restrict__ outp)
{
    extern __shared__ __align__(16) float sm[];
    float* Qs = sm + QS_OFF;
    float* Ks = sm + KS_OFF;
    float* Ps = sm + PS_OFF;
    float* Vs = sm + VS_OFF;

    const int qb = (int)gridDim.x - 1 - (int)blockIdx.x;  // heavy tiles first
    const int h  = blockIdx.y;
    const int b  = blockIdx.z;
    const int tid = threadIdx.x;
    const int wid = tid >> 5, lane = tid & 31;
    const int gid = lane >> 2, tig = lane & 3;

    const float* base = qkv + (size_t)b * S_ * C3;
    const int hoff = h * HD;
    const float qscale = 0.125f * 1.4426950408889634f;  // rsqrt(64) * log2(e)

    // Load Q tile: 128 x 64, scaled + tf32-rounded
    #pragma unroll
    for (int t = 0; t < 8; t++) {
        const int idx = tid + t * 256;
        const int r = idx >> 4, c4 = (idx & 15) << 2;
        float4 v = *(const float4*)(base + (size_t)(qb * 128 + r) * C3 + hoff + c4);
        v.x = cvt_tf32(v.x * qscale); v.y = cvt_tf32(v.y * qscale);
        v.z = cvt_tf32(v.z * qscale); v.w = cvt_tf32(v.w * qscale);
        *(float4*)&Qs[r * FP + c4] = v;
    }

    float oacc[8][4];
    #pragma unroll
    for (int nb = 0; nb < 8; nb++)
        #pragma unroll
        for (int r = 0; r < 4; r++) oacc[nb][r] = 0.0f;
    float m0 = -1e30f, m1 = -1e30f, l0 = 0.0f, l1 = 0.0f;

    const int pr = wid * 16 + gid;          // row within CTA tile
    const int grow0 = qb * 128 + pr;        // global q row (frag row 0)
    const int grow1 = grow0 + 8;

    const int nkt = 2 * qb + 2;
    for (int kt = 0; kt < nkt; kt++) {
        __syncthreads();  // previous tile's Ks/Vs fully consumed
        // Load K, V tiles: 64 x 64 each, tf32-rounded
        #pragma unroll
        for (int t = 0; t < 4; t++) {
            const int idx = tid + t * 256;
            const int r = idx >> 4, c4 = (idx & 15) << 2;
            const float* kp = base + (size_t)(kt * 64 + r) * C3 + NST + hoff + c4;
            float4 kv = *(const float4*)kp;
            float4 vv = *(const float4*)(kp + NST);
            kv.x = cvt_tf32(kv.x); kv.y = cvt_tf32(kv.y);
            kv.z = cvt_tf32(kv.z); kv.w = cvt_tf32(kv.w);
            vv.x = cvt_tf32(vv.x); vv.y = cvt_tf32(vv.y);
            vv.z = cvt_tf32(vv.z); vv.w = cvt_tf32(vv.w);
            *(float4*)&Ks[r * FP + c4] = kv;
            *(float4*)&Vs[r * FPV + c4] = vv;
        }
        __syncthreads();

        // S = Q K^T (in log2 domain due to qscale)
        float sacc[8][4];
        #pragma unroll
        for (int nb = 0; nb < 8; nb++)
            #pragma unroll
            for (int r = 0; r < 4; r++) sacc[nb][r] = 0.0f;

        #pragma unroll
        for (int ks = 0; ks < 8; ks++) {
            uint32_t a[4];
            a[0] = __float_as_uint(Qs[pr * FP + ks * 8 + tig]);
            a[1] = __float_as_uint(Qs[(pr + 8) * FP + ks * 8 + tig]);
            a[2] = __float_as_uint(Qs[pr * FP + ks * 8 + tig + 4]);
            a[3] = __float_as_uint(Qs[(pr + 8) * FP + ks * 8 + tig + 4]);
            #pragma unroll
            for (int nb = 0; nb < 8; nb++) {
                uint32_t bb[2];
                bb[0] = __float_as_uint(Ks[(nb * 8 + gid) * FP + ks * 8 + tig]);
                bb[1] = __float_as_uint(Ks[(nb * 8 + gid) * FP + ks * 8 + tig + 4]);
                MMA_TF32(sacc[nb], a, bb);
            }
        }

        // Causal mask (only the two diagonal-crossing tiles need it)
        if (kt >= 2 * qb) {
            #pragma unroll
            for (int nb = 0; nb < 8; nb++) {
                const int c = kt * 64 + nb * 8 + 2 * tig;
                if (c > grow0)     sacc[nb][0] = -1e30f;
                if (c + 1 > grow0) sacc[nb][1] = -1e30f;
                if (c > grow1)     sacc[nb][2] = -1e30f;
                if (c + 1 > grow1) sacc[nb][3] = -1e30f;
            }
        }

        // Online softmax (log2 domain), quad reductions
        float mx0 = -1e30f, mx1 = -1e30f;
        #pragma unroll
        for (int nb = 0; nb < 8; nb++) {
            mx0 = fmaxf(mx0, fmaxf(sacc[nb][0], sacc[nb][1]));
            mx1 = fmaxf(mx1, fmaxf(sacc[nb][2], sacc[nb][3]));
        }
        mx0 = fmaxf(mx0, __shfl_xor_sync(0xffffffffu, mx0, 1));
        mx0 = fmaxf(mx0, __shfl_xor_sync(0xffffffffu, mx0, 2));
        mx1 = fmaxf(mx1, __shfl_xor_sync(0xffffffffu, mx1, 1));
        mx1 = fmaxf(mx1, __shfl_xor_sync(0xffffffffu, mx1, 2));
        const float mn0 = fmaxf(m0, mx0), mn1 = fmaxf(m1, mx1);
        const float al0 = exp2f(m0 - mn0), al1 = exp2f(m1 - mn1);
        float sum0 = 0.0f, sum1 = 0.0f;
        #pragma unroll
        for (int nb = 0; nb < 8; nb++) {
            sacc[nb][0] = exp2f(sacc[nb][0] - mn0);
            sacc[nb][1] = exp2f(sacc[nb][1] - mn0);
            sacc[nb][2] = exp2f(sacc[nb][2] - mn1);
            sacc[nb][3] = exp2f(sacc[nb][3] - mn1);
            sum0 += sacc[nb][0] + sacc[nb][1];
            sum1 += sacc[nb][2] + sacc[nb][3];
        }
        sum0 += __shfl_xor_sync(0xffffffffu, sum0, 1);
        sum0 += __shfl_xor_sync(0xffffffffu, sum0, 2);
        sum1 += __shfl_xor_sync(0xffffffffu, sum1, 1);
        sum1 += __shfl_xor_sync(0xffffffffu, sum1, 2);
        l0 = l0 * al0 + sum0;
        l1 = l1 * al1 + sum1;
        m0 = mn0; m1 = mn1;
        #pragma unroll
        for (int nb = 0; nb < 8; nb++) {
            oacc[nb][0] *= al0; oacc[nb][1] *= al0;
            oacc[nb][2] *= al1; oacc[nb][3] *= al1;
        }

        // Stage P (tf32-rounded) to smem for the PV mma
        #pragma unroll
        for (int nb = 0; nb < 8; nb++) {
            float2 p0 = make_float2(cvt_tf32(sacc[nb][0]), cvt_tf32(sacc[nb][1]));
            float2 p1 = make_float2(cvt_tf32(sacc[nb][2]), cvt_tf32(sacc[nb][3]));
            *(float2*)&Ps[pr * FP + nb * 8 + 2 * tig] = p0;
            *(float2*)&Ps[(pr + 8) * FP + nb * 8 + 2 * tig] = p1;
        }
        __syncwarp();

        // O += P V
        #pragma unroll
        for (int ks = 0; ks < 8; ks++) {
            uint32_t a[4];
            a[0] = __float_as_uint(Ps[pr * FP + ks * 8 + tig]);
            a[1] = __float_as_uint(Ps[(pr + 8) * FP + ks * 8 + tig]);
            a[2] = __float_as_uint(Ps[pr * FP + ks * 8 + tig + 4]);
            a[3] = __float_as_uint(Ps[(pr + 8) * FP + ks * 8 + tig + 4]);
            #pragma unroll
            for (int nb = 0; nb < 8; nb++) {
                uint32_t bb[2];
                bb[0] = __float_as_uint(Vs[(ks * 8 + tig) * FPV + nb * 8 + gid]);
                bb[1] = __float_as_uint(Vs[(ks * 8 + tig + 4) * FPV + nb * 8 + gid]);
                MMA_TF32(oacc[nb], a, bb);
            }
        }
    }

    // Epilogue: normalize, tf32-round, write merged heads
    const float inv0 = 1.0f / l0, inv1 = 1.0f / l1;
    float* orow0 = outp + ((size_t)b * S_ + grow0) * NST + hoff;
    float* orow1 = outp + ((size_t)b * S_ + grow1) * NST + hoff;
    #pragma unroll
    for (int nb = 0; nb < 8; nb++) {
        const int c = nb * 8 + 2 * tig;
        float2 v0 = make_float2(cvt_tf32(oacc[nb][0] * inv0),
                                cvt_tf32(oacc[nb][1] * inv0));
        float2 v1 = make_float2(cvt_tf32(oacc[nb][2] * inv1),
                                cvt_tf32(oacc[nb][3] * inv1));
        *(float2*)(orow0 + c) = v0;
        *(float2*)(orow1 + c) = v1;
    }
}

// ---------------------------------------------------------------------------
extern "C" void kernel_launch(void* const* d_in, const int* in_sizes, int n_in,
                              void* d_out, int out_size)
{
    const float* x   = (const float*)d_in[0];
    const float* w_c = (const float*)d_in[1];
    const float* b_c = (const float*)d_in[2];
    const float* w_p = (const float*)d_in[3];
    const float* b_p = (const float*)d_in[4];
    float* out = (float*)d_out;

    void *qkv_p, *attn_p, *xr_p, *wct_p, *wpt_p;
    cudaGetSymbolAddress(&qkv_p, g_qkv);
    cudaGetSymbolAddress(&attn_p, g_attn);
    cudaGetSymbolAddress(&xr_p, g_xr);
    cudaGetSymbolAddress(&wct_p, g_wct);
    cudaGetSymbolAddress(&wpt_p, g_wpt);
    float* qkv  = (float*)qkv_p;
    float* attn = (float*)attn_p;
    float* xr   = (float*)xr_p;
    float* wct  = (float*)wct_p;
    float* wpt  = (float*)wpt_p;

    static bool attr_done = false;
    if (!attr_done) {
        cudaFuncSetAttribute(gemm_mma_kernel,
                             cudaFuncAttributeMaxDynamicSharedMemorySize, GEMM_SMEM);
        cudaFuncSetAttribute(flash_mma_kernel,
                             cudaFuncAttributeMaxDynamicSharedMemorySize, FLASH_SMEM);
        attr_done = true;
    }

    // 0) tf32-round x; transpose + round weights
    round_tf32_kernel<<<(MROWS * NX_ / 4 + 255) / 256, 256>>>(x, xr, MROWS * NX_ / 4);
    transpose_round_kernel<<<dim3(C3 / 32, NX_ / 32), dim3(32, 8)>>>(w_c, wct, NX_, C3);
    transpose_round_kernel<<<dim3(NST / 32, NX_ / 32), dim3(32, 8)>>>(w_p, wpt, NX_, NST);

    // 1) QKV projection (tf32 tensor cores)
    gemm_mma_kernel<<<dim3(C3 / GBN, MROWS / GBM), 256, GEMM_SMEM>>>(
        xr, wct, b_c, qkv, MROWS, C3, NX_);

    // 2) Flash attention (tf32 tensor cores)
    flash_mma_kernel<<<dim3(S_ / 128, NH, B_), 256, FLASH_SMEM>>>(qkv, attn);

    // 3) Output projection (tf32 tensor cores)
    gemm_mma_kernel<<<dim3(NST / GBN, MROWS / GBM), 256, GEMM_SMEM>>>(
        attn, wpt, b_p, out, MROWS, NST, NX_);
}

// round 6
// speedup vs baseline: 3.1090x; 1.2072x over previous
#include <cuda_runtime.h>
#include <math_constants.h>
#include <cstdint>

#define B_    2
#define S_    2048
#define NX_   1024
#define NST   1024
#define NH    16
#define HD    64
#define MROWS 4096
#define C3    3072

// Scratch (no allocations allowed)
__device__ float g_qkv[MROWS * C3];    // [4096, 3072]  (q|k|v)
__device__ float g_attn[MROWS * NST];  // [4096, 1024]  merged heads (tf32-rounded)
__device__ float g_xr[MROWS * NX_];    // x, tf32-rounded
__device__ float g_wct[C3 * NX_];      // w_c transposed [3072,1024], tf32-rounded
__device__ float g_wpt[NST * NX_];     // w_p transposed [1024,1024], tf32-rounded

__device__ __forceinline__ float cvt_tf32(float x) {
    float y;
    asm("cvt.rna.tf32.f32 %0, %1;" : "=f"(y) : "f"(x));
    return y;
}
__device__ __forceinline__ uint32_t smem_u32(const void* p) {
    uint32_t a;
    asm("{ .reg .u64 t; cvta.to.shared.u64 t, %1; cvt.u32.u64 %0, t; }"
        : "=r"(a) : "l"(p));
    return a;
}
#define CP_ASYNC16(smaddr, gptr) \
    asm volatile("cp.async.cg.shared.global [%0], [%1], 16;" \
                 :: "r"(smaddr), "l"(gptr) : "memory")
#define CP_COMMIT() asm volatile("cp.async.commit_group;" ::: "memory")
#define CP_WAIT1()  asm volatile("cp.async.wait_group 1;" ::: "memory")

#define MMA_TF32(acc, a, b)                                                    \
    asm volatile(                                                              \
        "mma.sync.aligned.m16n8k8.row.col.f32.tf32.tf32.f32 "                  \
        "{%0,%1,%2,%3}, {%4,%5,%6,%7}, {%8,%9}, {%0,%1,%2,%3};"                \
        : "+f"((acc)[0]), "+f"((acc)[1]), "+f"((acc)[2]), "+f"((acc)[3])       \
        : "r"((a)[0]), "r"((a)[1]), "r"((a)[2]), "r"((a)[3]),                  \
          "r"((b)[0]), "r"((b)[1]))

// ---------------------------------------------------------------------------
// Elementwise tf32 rounding
// ---------------------------------------------------------------------------
__global__ __launch_bounds__(256) void round_tf32_kernel(
    const float* __restrict__ in, float* __restrict__ out, int n4)
{
    int i = blockIdx.x * 256 + threadIdx.x;
    if (i < n4) {
        float4 v = ((const float4*)in)[i];
        v.x = cvt_tf32(v.x); v.y = cvt_tf32(v.y);
        v.z = cvt_tf32(v.z); v.w = cvt_tf32(v.w);
        ((float4*)out)[i] = v;
    }
}

// ---------------------------------------------------------------------------
// Transpose + tf32 round:  WT[n*K + k] = tf32(W[k*N + n])
// ---------------------------------------------------------------------------
__global__ __launch_bounds__(256) void transpose_round_kernel(
    const float* __restrict__ W, float* __restrict__ WT, int K, int N)
{
    __shared__ float t[32][33];
    const int tx = threadIdx.x, ty = threadIdx.y;
    const int n0 = blockIdx.x * 32, k0 = blockIdx.y * 32;
    #pragma unroll
    for (int i = 0; i < 32; i += 8)
        t[ty + i][tx] = W[(size_t)(k0 + ty + i) * N + n0 + tx];
    __syncthreads();
    #pragma unroll
    for (int i = 0; i < 32; i += 8)
        WT[(size_t)(n0 + ty + i) * K + k0 + tx] = cvt_tf32(t[tx][ty + i]);
}

// ---------------------------------------------------------------------------
// tf32 mma.sync GEMM:  C[M,N] = A[M,K] @ BT[N,K]^T + bias
// BM=128, BN=128, BK=32. 256 threads = 8 warps (2x4), 64x32 per warp.
// 3-stage cp.async pipeline, ONE barrier per chunk:
//   wait_group 1 -> barrier -> prefetch(kc+2) -> commit -> 4x(k8 frag+mma).
// Safety: barrier at iter kc proves all threads finished MMAs on stage
// (kc-1)%3 == (kc+2)%3, the stage prefetch overwrites; each thread's own
// wait before the barrier makes stage-kc cp.async data visible to all.
// Smem pitch 36 floats (144 B, 16B-aligned rows; banks 4*gid+tig distinct).
// ---------------------------------------------------------------------------
#define GBM 128
#define GBN 128
#define GBK 32
#define TPITCH 36
#define TILE_F (128 * TPITCH)
#define GEMM_SMEM (6 * TILE_F * 4)       // 110592 B

__global__ __launch_bounds__(256) void gemm_mma_kernel(
    const float* __restrict__ A, const float* __restrict__ BT,
    const float* __restrict__ bias, float* __restrict__ C,
    int M, int N, int K)
{
    extern __shared__ __align__(16) float smf[];
    const uint32_t smb = smem_u32(smf);

    const int tid = threadIdx.x;
    const int wid = tid >> 5, lane = tid & 31;
    const int gid = lane >> 2, tig = lane & 3;
    const int warp_m = wid & 1, warp_n = wid >> 1;

    const int m0 = blockIdx.y * GBM;
    const int n0 = blockIdx.x * GBN;

    // cp.async mapping: per tile (128x32 floats = 1024 float4), each of 256
    // threads copies 4 float4: rows tid>>3 + {0,32,64,96}, col (tid&7)*4.
    const int cr = tid >> 3;
    const int cc = (tid & 7) << 2;

    const float* Ap = A + (size_t)m0 * K;
    const float* Bp = BT + (size_t)n0 * K;

    const int nchunk = K / GBK;

    float acc[4][4][4];
    #pragma unroll
    for (int i = 0; i < 4; i++)
        #pragma unroll
        for (int j = 0; j < 4; j++)
            #pragma unroll
            for (int r = 0; r < 4; r++) acc[i][j][r] = 0.0f;

    #define PREFETCH(kc, st) do {                                               \
        const uint32_t abase = smb + (st) * TILE_F * 4;                         \
        const uint32_t bbase = smb + (3 + (st)) * TILE_F * 4;                   \
        _Pragma("unroll")                                                       \
        for (int s = 0; s < 4; s++) {                                           \
            const int rr = cr + s * 32;                                         \
            CP_ASYNC16(abase + (rr * TPITCH + cc) * 4,                          \
                       Ap + (size_t)rr * K + (kc) * GBK + cc);                  \
            CP_ASYNC16(bbase + (rr * TPITCH + cc) * 4,                          \
                       Bp + (size_t)rr * K + (kc) * GBK + cc);                  \
        }                                                                       \
    } while (0)

    PREFETCH(0, 0); CP_COMMIT();
    PREFETCH(1, 1); CP_COMMIT();

    for (int kc = 0; kc < nchunk; kc++) {
        const int st = kc % 3;
        CP_WAIT1();                            // group kc complete (own thread)
        __syncthreads();                       // all threads: stage kc visible,
                                               // stage (kc+2)%3 fully consumed
        if (kc + 2 < nchunk) { PREFETCH(kc + 2, (kc + 2) % 3); }
        CP_COMMIT();

        const float* As = smf + st * TILE_F;
        const float* Bs = smf + (3 + st) * TILE_F;

        #pragma unroll
        for (int k0 = 0; k0 < GBK; k0 += 8) {
            uint32_t afr[4][4], bfr[4][2];
            #pragma unroll
            for (int i = 0; i < 4; i++) {
                const int mr = warp_m * 64 + i * 16 + gid;
                afr[i][0] = __float_as_uint(As[mr * TPITCH + k0 + tig]);
                afr[i][1] = __float_as_uint(As[(mr + 8) * TPITCH + k0 + tig]);
                afr[i][2] = __float_as_uint(As[mr * TPITCH + k0 + tig + 4]);
                afr[i][3] = __float_as_uint(As[(mr + 8) * TPITCH + k0 + tig + 4]);
            }
            #pragma unroll
            for (int j = 0; j < 4; j++) {
                const int nc = warp_n * 32 + j * 8 + gid;
                bfr[j][0] = __float_as_uint(Bs[nc * TPITCH + k0 + tig]);
                bfr[j][1] = __float_as_uint(Bs[nc * TPITCH + k0 + tig + 4]);
            }
            #pragma unroll
            for (int i = 0; i < 4; i++)
                #pragma unroll
                for (int j = 0; j < 4; j++)
                    MMA_TF32(acc[i][j], afr[i], bfr[j]);
        }
    }

    #pragma unroll
    for (int i = 0; i < 4; i++) {
        const int r0 = m0 + warp_m * 64 + i * 16 + gid;
        #pragma unroll
        for (int j = 0; j < 4; j++) {
            const int col = n0 + warp_n * 32 + j * 8 + 2 * tig;
            const float bx = bias[col], by = bias[col + 1];
            float2 v0 = make_float2(acc[i][j][0] + bx, acc[i][j][1] + by);
            float2 v1 = make_float2(acc[i][j][2] + bx, acc[i][j][3] + by);
            *(float2*)(C + (size_t)r0 * N + col) = v0;
            *(float2*)(C + (size_t)(r0 + 8) * N + col) = v1;
        }
    }
}

// ---------------------------------------------------------------------------
// Tensor-core flash attention (tf32 mma.sync) — unchanged from R5.
// ---------------------------------------------------------------------------
#define FP  68
#define FPV 72
#define QS_OFF 0
#define KS_OFF (128 * FP)
#define PS_OFF (192 * FP)
#define VS_OFF (320 * FP)
#define FLASH_SMEM ((320 * FP + 64 * FPV) * 4)   // 105472 B

__global__ __launch_bounds__(256) void flash_mma_kernel(
    const float* __restrict__ qkv, float* __restrict__ outp)
{
    extern __shared__ __align__(16) float sm[];
    float* Qs = sm + QS_OFF;
    float* Ks = sm + KS_OFF;
    float* Ps = sm + PS_OFF;
    float* Vs = sm + VS_OFF;

    const int qb = (int)gridDim.x - 1 - (int)blockIdx.x;
    const int h  = blockIdx.y;
    const int b  = blockIdx.z;
    const int tid = threadIdx.x;
    const int wid = tid >> 5, lane = tid & 31;
    const int gid = lane >> 2, tig = lane & 3;

    const float* base = qkv + (size_t)b * S_ * C3;
    const int hoff = h * HD;
    const float qscale = 0.125f * 1.4426950408889634f;

    #pragma unroll
    for (int t = 0; t < 8; t++) {
        const int idx = tid + t * 256;
        const int r = idx >> 4, c4 = (idx & 15) << 2;
        float4 v = *(const float4*)(base + (size_t)(qb * 128 + r) * C3 + hoff + c4);
        v.x = cvt_tf32(v.x * qscale); v.y = cvt_tf32(v.y * qscale);
        v.z = cvt_tf32(v.z * qscale); v.w = cvt_tf32(v.w * qscale);
        *(float4*)&Qs[r * FP + c4] = v;
    }

    float oacc[8][4];
    #pragma unroll
    for (int nb = 0; nb < 8; nb++)
        #pragma unroll
        for (int r = 0; r < 4; r++) oacc[nb][r] = 0.0f;
    float m0 = -1e30f, m1 = -1e30f, l0 = 0.0f, l1 = 0.0f;

    const int pr = wid * 16 + gid;
    const int grow0 = qb * 128 + pr;
    const int grow1 = grow0 + 8;

    const int nkt = 2 * qb + 2;
    for (int kt = 0; kt < nkt; kt++) {
        __syncthreads();
        #pragma unroll
        for (int t = 0; t < 4; t++) {
            const int idx = tid + t * 256;
            const int r = idx >> 4, c4 = (idx & 15) << 2;
            const float* kp = base + (size_t)(kt * 64 + r) * C3 + NST + hoff + c4;
            float4 kv = *(const float4*)kp;
            float4 vv = *(const float4*)(kp + NST);
            kv.x = cvt_tf32(kv.x); kv.y = cvt_tf32(kv.y);
            kv.z = cvt_tf32(kv.z); kv.w = cvt_tf32(kv.w);
            vv.x = cvt_tf32(vv.x); vv.y = cvt_tf32(vv.y);
            vv.z = cvt_tf32(vv.z); vv.w = cvt_tf32(vv.w);
            *(float4*)&Ks[r * FP + c4] = kv;
            *(float4*)&Vs[r * FPV + c4] = vv;
        }
        __syncthreads();

        float sacc[8][4];
        #pragma unroll
        for (int nb = 0; nb < 8; nb++)
            #pragma unroll
            for (int r = 0; r < 4; r++) sacc[nb][r] = 0.0f;

        #pragma unroll
        for (int ks = 0; ks < 8; ks++) {
            uint32_t a[4];
            a[0] = __float_as_uint(Qs[pr * FP + ks * 8 + tig]);
            a[1] = __float_as_uint(Qs[(pr + 8) * FP + ks * 8 + tig]);
            a[2] = __float_as_uint(Qs[pr * FP + ks * 8 + tig + 4]);
            a[3] = __float_as_uint(Qs[(pr + 8) * FP + ks * 8 + tig + 4]);
            #pragma unroll
            for (int nb = 0; nb < 8; nb++) {
                uint32_t bb[2];
                bb[0] = __float_as_uint(Ks[(nb * 8 + gid) * FP + ks * 8 + tig]);
                bb[1] = __float_as_uint(Ks[(nb * 8 + gid) * FP + ks * 8 + tig + 4]);
                MMA_TF32(sacc[nb], a, bb);
            }
        }

        if (kt >= 2 * qb) {
            #pragma unroll
            for (int nb = 0; nb < 8; nb++) {
                const int c = kt * 64 + nb * 8 + 2 * tig;
                if (c > grow0)     sacc[nb][0] = -1e30f;
                if (c + 1 > grow0) sacc[nb][1] = -1e30f;
                if (c > grow1)     sacc[nb][2] = -1e30f;
                if (c + 1 > grow1) sacc[nb][3] = -1e30f;
            }
        }

        float mx0 = -1e30f, mx1 = -1e30f;
        #pragma unroll
        for (int nb = 0; nb < 8; nb++) {
            mx0 = fmaxf(mx0, fmaxf(sacc[nb][0], sacc[nb][1]));
            mx1 = fmaxf(mx1, fmaxf(sacc[nb][2], sacc[nb][3]));
        }
        mx0 = fmaxf(mx0, __shfl_xor_sync(0xffffffffu, mx0, 1));
        mx0 = fmaxf(mx0, __shfl_xor_sync(0xffffffffu, mx0, 2));
        mx1 = fmaxf(mx1, __shfl_xor_sync(0xffffffffu, mx1, 1));
        mx1 = fmaxf(mx1, __shfl_xor_sync(0xffffffffu, mx1, 2));
        const float mn0 = fmaxf(m0, mx0), mn1 = fmaxf(m1, mx1);
        const float al0 = exp2f(m0 - mn0), al1 = exp2f(m1 - mn1);
        float sum0 = 0.0f, sum1 = 0.0f;
        #pragma unroll
        for (int nb = 0; nb < 8; nb++) {
            sacc[nb][0] = exp2f(sacc[nb][0] - mn0);
            sacc[nb][1] = exp2f(sacc[nb][1] - mn0);
            sacc[nb][2] = exp2f(sacc[nb][2] - mn1);
            sacc[nb][3] = exp2f(sacc[nb][3] - mn1);
            sum0 += sacc[nb][0] + sacc[nb][1];
            sum1 += sacc[nb][2] + sacc[nb][3];
        }
        sum0 += __shfl_xor_sync(0xffffffffu, sum0, 1);
        sum0 += __shfl_xor_sync(0xffffffffu, sum0, 2);
        sum1 += __shfl_xor_sync(0xffffffffu, sum1, 1);
        sum1 += __shfl_xor_sync(0xffffffffu, sum1, 2);
        l0 = l0 * al0 + sum0;
        l1 = l1 * al1 + sum1;
        m0 = mn0; m1 = mn1;
        #pragma unroll
        for (int nb = 0; nb < 8; nb++) {
            oacc[nb][0] *= al0; oacc[nb][1] *= al0;
            oacc[nb][2] *= al1; oacc[nb][3] *= al1;
        }

        #pragma unroll
        for (int nb = 0; nb < 8; nb++) {
            float2 p0 = make_float2(cvt_tf32(sacc[nb][0]), cvt_tf32(sacc[nb][1]));
            float2 p1 = make_float2(cvt_tf32(sacc[nb][2]), cvt_tf32(sacc[nb][3]));
            *(float2*)&Ps[pr * FP + nb * 8 + 2 * tig] = p0;
            *(float2*)&Ps[(pr + 8) * FP + nb * 8 + 2 * tig] = p1;
        }
        __syncwarp();

        #pragma unroll
        for (int ks = 0; ks < 8; ks++) {
            uint32_t a[4];
            a[0] = __float_as_uint(Ps[pr * FP + ks * 8 + tig]);
            a[1] = __float_as_uint(Ps[(pr + 8) * FP + ks * 8 + tig]);
            a[2] = __float_as_uint(Ps[pr * FP + ks * 8 + tig + 4]);
            a[3] = __float_as_uint(Ps[(pr + 8) * FP + ks * 8 + tig + 4]);
            #pragma unroll
            for (int nb = 0; nb < 8; nb++) {
                uint32_t bb[2];
                bb[0] = __float_as_uint(Vs[(ks * 8 + tig) * FPV + nb * 8 + gid]);
                bb[1] = __float_as_uint(Vs[(ks * 8 + tig + 4) * FPV + nb * 8 + gid]);
                MMA_TF32(oacc[nb], a, bb);
            }
        }
    }

    const float inv0 = 1.0f / l0, inv1 = 1.0f / l1;
    float* orow0 = outp + ((size_t)b * S_ + grow0) * NST + hoff;
    float* orow1 = outp + ((size_t)b * S_ + grow1) * NST + hoff;
    #pragma unroll
    for (int nb = 0; nb < 8; nb++) {
        const int c = nb * 8 + 2 * tig;
        float2 v0 = make_float2(cvt_tf32(oacc[nb][0] * inv0),
                                cvt_tf32(oacc[nb][1] * inv0));
        float2 v1 = make_float2(cvt_tf32(oacc[nb][2] * inv1),
                                cvt_tf32(oacc[nb][3] * inv1));
        *(float2*)(orow0 + c) = v0;
        *(float2*)(orow1 + c) = v1;
    }
}

// ---------------------------------------------------------------------------
extern "C" void kernel_launch(void* const* d_in, const int* in_sizes, int n_in,
                              void* d_out, int out_size)
{
    const float* x   = (const float*)d_in[0];
    const float* w_c = (const float*)d_in[1];
    const float* b_c = (const float*)d_in[2];
    const float* w_p = (const float*)d_in[3];
    const float* b_p = (const float*)d_in[4];
    float* out = (float*)d_out;

    void *qkv_p, *attn_p, *xr_p, *wct_p, *wpt_p;
    cudaGetSymbolAddress(&qkv_p, g_qkv);
    cudaGetSymbolAddress(&attn_p, g_attn);
    cudaGetSymbolAddress(&xr_p, g_xr);
    cudaGetSymbolAddress(&wct_p, g_wct);
    cudaGetSymbolAddress(&wpt_p, g_wpt);
    float* qkv  = (float*)qkv_p;
    float* attn = (float*)attn_p;
    float* xr   = (float*)xr_p;
    float* wct  = (float*)wct_p;
    float* wpt  = (float*)wpt_p;

    static bool attr_done = false;
    if (!attr_done) {
        cudaFuncSetAttribute(gemm_mma_kernel,
                             cudaFuncAttributeMaxDynamicSharedMemorySize, GEMM_SMEM);
        cudaFuncSetAttribute(flash_mma_kernel,
                             cudaFuncAttributeMaxDynamicSharedMemorySize, FLASH_SMEM);
        attr_done = true;
    }

    // 0) tf32-round x; transpose + round weights
    round_tf32_kernel<<<(MROWS * NX_ / 4 + 255) / 256, 256>>>(x, xr, MROWS * NX_ / 4);
    transpose_round_kernel<<<dim3(C3 / 32, NX_ / 32), dim3(32, 8)>>>(w_c, wct, NX_, C3);
    transpose_round_kernel<<<dim3(NST / 32, NX_ / 32), dim3(32, 8)>>>(w_p, wpt, NX_, NST);

    // 1) QKV projection (tf32 tensor cores)
    gemm_mma_kernel<<<dim3(C3 / GBN, MROWS / GBM), 256, GEMM_SMEM>>>(
        xr, wct, b_c, qkv, MROWS, C3, NX_);

    // 2) Flash attention (tf32 tensor cores)
    flash_mma_kernel<<<dim3(S_ / 128, NH, B_), 256, FLASH_SMEM>>>(qkv, attn);

    // 3) Output projection (tf32 tensor cores)
    gemm_mma_kernel<<<dim3(NST / GBN, MROWS / GBM), 256, GEMM_SMEM>>>(
        attn, wpt, b_p, out, MROWS, NST, NX_);
}

// round 7
// speedup vs baseline: 3.7885x; 1.2186x over previous
#include <cuda_runtime.h>
#include <math_constants.h>
#include <cuda_fp16.h>
#include <cstdint>

#define B_    2
#define S_    2048
#define NX_   1024
#define NST   1024
#define NH    16
#define HD    64
#define MROWS 4096
#define C3    3072

// Scratch (no allocations allowed)
__device__ float  g_qkv[MROWS * C3];   // [4096, 3072] q|k|v, q/k tf32-rounded
__device__ __half g_vh[MROWS * NST];   // v as fp16 (for flash PV)
__device__ float  g_attn[MROWS * NST]; // merged heads (tf32-rounded)
__device__ float  g_xr[MROWS * NX_];   // x, tf32-rounded
__device__ float  g_wct[C3 * NX_];     // w_c^T, tf32-rounded
__device__ float  g_wpt[NST * NX_];    // w_p^T, tf32-rounded

__device__ __forceinline__ float cvt_tf32(float x) {
    float y;
    asm("cvt.rna.tf32.f32 %0, %1;" : "=f"(y) : "f"(x));
    return y;
}
__device__ __forceinline__ uint32_t smem_u32(const void* p) {
    uint32_t a;
    asm("{ .reg .u64 t; cvta.to.shared.u64 t, %1; cvt.u32.u64 %0, t; }"
        : "=r"(a) : "l"(p));
    return a;
}
__device__ __forceinline__ uint32_t pack_h2(float lo, float hi) {
    uint32_t r;
    asm("cvt.rn.f16x2.f32 %0, %1, %2;" : "=r"(r) : "f"(hi), "f"(lo));
    return r;
}
#define CP_ASYNC16(smaddr, gptr) \
    asm volatile("cp.async.cg.shared.global [%0], [%1], 16;" \
                 :: "r"(smaddr), "l"(gptr) : "memory")
#define CP_COMMIT() asm volatile("cp.async.commit_group;" ::: "memory")
#define CP_WAIT1()  asm volatile("cp.async.wait_group 1;" ::: "memory")

#define MMA_TF32(acc, a, b)                                                    \
    asm volatile(                                                              \
        "mma.sync.aligned.m16n8k8.row.col.f32.tf32.tf32.f32 "                  \
        "{%0,%1,%2,%3}, {%4,%5,%6,%7}, {%8,%9}, {%0,%1,%2,%3};"                \
        : "+f"((acc)[0]), "+f"((acc)[1]), "+f"((acc)[2]), "+f"((acc)[3])       \
        : "r"((a)[0]), "r"((a)[1]), "r"((a)[2]), "r"((a)[3]),                  \
          "r"((b)[0]), "r"((b)[1]))

#define MMA_F16(acc, a, b0, b1)                                                \
    asm volatile(                                                              \
        "mma.sync.aligned.m16n8k16.row.col.f32.f16.f16.f32 "                   \
        "{%0,%1,%2,%3}, {%4,%5,%6,%7}, {%8,%9}, {%0,%1,%2,%3};"                \
        : "+f"((acc)[0]), "+f"((acc)[1]), "+f"((acc)[2]), "+f"((acc)[3])       \
        : "r"((a)[0]), "r"((a)[1]), "r"((a)[2]), "r"((a)[3]),                  \
          "r"(b0), "r"(b1))

#define LDMX4T(r0, r1, r2, r3, addr)                                           \
    asm volatile(                                                              \
        "ldmatrix.sync.aligned.m8n8.x4.trans.shared.b16 {%0,%1,%2,%3}, [%4];"  \
        : "=r"(r0), "=r"(r1), "=r"(r2), "=r"(r3) : "r"(addr))

// ---------------------------------------------------------------------------
__global__ __launch_bounds__(256) void round_tf32_kernel(
    const float* __restrict__ in, float* __restrict__ out, int n4)
{
    int i = blockIdx.x * 256 + threadIdx.x;
    if (i < n4) {
        float4 v = ((const float4*)in)[i];
        v.x = cvt_tf32(v.x); v.y = cvt_tf32(v.y);
        v.z = cvt_tf32(v.z); v.w = cvt_tf32(v.w);
        ((float4*)out)[i] = v;
    }
}

__global__ __launch_bounds__(256) void transpose_round_kernel(
    const float* __restrict__ W, float* __restrict__ WT, int K, int N)
{
    __shared__ float t[32][33];
    const int tx = threadIdx.x, ty = threadIdx.y;
    const int n0 = blockIdx.x * 32, k0 = blockIdx.y * 32;
    #pragma unroll
    for (int i = 0; i < 32; i += 8)
        t[ty + i][tx] = W[(size_t)(k0 + ty + i) * N + n0 + tx];
    __syncthreads();
    #pragma unroll
    for (int i = 0; i < 32; i += 8)
        WT[(size_t)(n0 + ty + i) * K + k0 + tx] = cvt_tf32(t[tx][ty + i]);
}

// ---------------------------------------------------------------------------
// tf32 mma.sync GEMM. BM=128,BN=128,BK=32, 8 warps, 3-stage cp.async,
// one barrier per chunk. qkv_mode=1: outputs tf32-rounded; v-range cols
// (n >= 2048) additionally written as fp16 to VH[row*1024 + n-2048].
// ---------------------------------------------------------------------------
#define GBM 128
#define GBN 128
#define GBK 32
#define TPITCH 36
#define TILE_F (128 * TPITCH)
#define GEMM_SMEM (6 * TILE_F * 4)       // 110592 B

__global__ __launch_bounds__(256, 2) void gemm_mma_kernel(
    const float* __restrict__ A, const float* __restrict__ BT,
    const float* __restrict__ bias, float* __restrict__ C,
    __half* __restrict__ VH, int qkv_mode,
    int M, int N, int K)
{
    extern __shared__ __align__(16) float smf[];
    const uint32_t smb = smem_u32(smf);

    const int tid = threadIdx.x;
    const int wid = tid >> 5, lane = tid & 31;
    const int gid = lane >> 2, tig = lane & 3;
    const int warp_m = wid & 1, warp_n = wid >> 1;

    const int m0 = blockIdx.y * GBM;
    const int n0 = blockIdx.x * GBN;

    const int cr = tid >> 3;
    const int cc = (tid & 7) << 2;

    const float* Ap = A + (size_t)m0 * K;
    const float* Bp = BT + (size_t)n0 * K;

    const int nchunk = K / GBK;

    float acc[4][4][4];
    #pragma unroll
    for (int i = 0; i < 4; i++)
        #pragma unroll
        for (int j = 0; j < 4; j++)
            #pragma unroll
            for (int r = 0; r < 4; r++) acc[i][j][r] = 0.0f;

    #define PREFETCH(kc, st) do {                                               \
        const uint32_t abase = smb + (st) * TILE_F * 4;                         \
        const uint32_t bbase = smb + (3 + (st)) * TILE_F * 4;                   \
        _Pragma("unroll")                                                       \
        for (int s = 0; s < 4; s++) {                                           \
            const int rr = cr + s * 32;                                         \
            CP_ASYNC16(abase + (rr * TPITCH + cc) * 4,                          \
                       Ap + (size_t)rr * K + (kc) * GBK + cc);                  \
            CP_ASYNC16(bbase + (rr * TPITCH + cc) * 4,                          \
                       Bp + (size_t)rr * K + (kc) * GBK + cc);                  \
        }                                                                       \
    } while (0)

    PREFETCH(0, 0); CP_COMMIT();
    PREFETCH(1, 1); CP_COMMIT();

    for (int kc = 0; kc < nchunk; kc++) {
        const int st = kc % 3;
        CP_WAIT1();
        __syncthreads();
        if (kc + 2 < nchunk) { PREFETCH(kc + 2, (kc + 2) % 3); }
        CP_COMMIT();

        const float* As = smf + st * TILE_F;
        const float* Bs = smf + (3 + st) * TILE_F;

        #pragma unroll
        for (int k0 = 0; k0 < GBK; k0 += 8) {
            uint32_t afr[4][4], bfr[4][2];
            #pragma unroll
            for (int i = 0; i < 4; i++) {
                const int mr = warp_m * 64 + i * 16 + gid;
                afr[i][0] = __float_as_uint(As[mr * TPITCH + k0 + tig]);
                afr[i][1] = __float_as_uint(As[(mr + 8) * TPITCH + k0 + tig]);
                afr[i][2] = __float_as_uint(As[mr * TPITCH + k0 + tig + 4]);
                afr[i][3] = __float_as_uint(As[(mr + 8) * TPITCH + k0 + tig + 4]);
            }
            #pragma unroll
            for (int j = 0; j < 4; j++) {
                const int nc = warp_n * 32 + j * 8 + gid;
                bfr[j][0] = __float_as_uint(Bs[nc * TPITCH + k0 + tig]);
                bfr[j][1] = __float_as_uint(Bs[nc * TPITCH + k0 + tig + 4]);
            }
            #pragma unroll
            for (int i = 0; i < 4; i++)
                #pragma unroll
                for (int j = 0; j < 4; j++)
                    MMA_TF32(acc[i][j], afr[i], bfr[j]);
        }
    }

    const bool vrange = qkv_mode && (n0 >= 2 * NST);
    #pragma unroll
    for (int i = 0; i < 4; i++) {
        const int r0 = m0 + warp_m * 64 + i * 16 + gid;
        #pragma unroll
        for (int j = 0; j < 4; j++) {
            const int col = n0 + warp_n * 32 + j * 8 + 2 * tig;
            const float bx = bias[col], by = bias[col + 1];
            float2 v0 = make_float2(acc[i][j][0] + bx, acc[i][j][1] + by);
            float2 v1 = make_float2(acc[i][j][2] + bx, acc[i][j][3] + by);
            if (qkv_mode) {
                v0.x = cvt_tf32(v0.x); v0.y = cvt_tf32(v0.y);
                v1.x = cvt_tf32(v1.x); v1.y = cvt_tf32(v1.y);
                if (vrange) {
                    const int vc = col - 2 * NST;
                    *(__half2*)(VH + (size_t)r0 * NST + vc) =
                        __floats2half2_rn(v0.x, v0.y);
                    *(__half2*)(VH + (size_t)(r0 + 8) * NST + vc) =
                        __floats2half2_rn(v1.x, v1.y);
                }
            }
            *(float2*)(C + (size_t)r0 * N + col) = v0;
            *(float2*)(C + (size_t)(r0 + 8) * N + col) = v1;
        }
    }
}

// ---------------------------------------------------------------------------
// Flash attention: QK^T in tf32 mma (K from double-buffered cp.async smem,
// operands pre-rounded by the QKV GEMM), softmax in f32 (scale applied
// post-mma, log2 domain), PV in fp16 m16n8k16 with P kept in registers
// (QK C-frag == fp16 A-frag layout) and V b-frags via ldmatrix.x4.trans.
// Smem: Q 128x68 f32 | K 2x 64x68 f32 | V 2x 64x72 fp16 = 88064 B.
// ---------------------------------------------------------------------------
#define FQP 68
#define FKP 68
#define FVP 72                              // halves
#define KS_OFF 8704                         // floats
#define KSTG   4352                         // floats
#define VH_OFF 69632                        // bytes
#define VSTG   9216                         // bytes
#define FLASH_SMEM (VH_OFF + 2 * VSTG)      // 88064 B

__global__ __launch_bounds__(256, 2) void flash_mma_kernel(
    const float* __restrict__ qkv, const __half* __restrict__ vh,
    float* __restrict__ outp)
{
    extern __shared__ __align__(16) float sm[];
    const uint32_t smb = smem_u32(sm);
    float* Qs = sm;

    const int qb = (int)gridDim.x - 1 - (int)blockIdx.x;
    const int h  = blockIdx.y;
    const int b  = blockIdx.z;
    const int tid = threadIdx.x;
    const int wid = tid >> 5, lane = tid & 31;
    const int gid = lane >> 2, tig = lane & 3;

    const int hoff = h * HD;
    const float* qptr = qkv + (size_t)b * S_ * C3 + (size_t)qb * 128 * C3 + hoff;
    const float* kptr = qkv + (size_t)b * S_ * C3 + NST + hoff;
    const __half* vptr = vh + (size_t)b * S_ * NST + hoff;
    const float qls = 0.125f * 1.4426950408889634f;   // rsqrt(64)*log2(e)

    // Q tile via cp.async (group 0): 128 rows x 64 f32
    {
        const int r = tid >> 1;
        #pragma unroll
        for (int s = 0; s < 8; s++) {
            const int c = ((tid & 1) + 2 * s) * 4;
            CP_ASYNC16(smb + (r * FQP + c) * 4, qptr + (size_t)r * C3 + c);
        }
        CP_COMMIT();
    }

    #define PREFETCH_KV(kt, st) do {                                            \
        const uint32_t kb = smb + (KS_OFF + (st) * KSTG) * 4;                    \
        const uint32_t vb = smb + VH_OFF + (st) * VSTG;                          \
        const int r_ = tid >> 2;                                                 \
        _Pragma("unroll")                                                        \
        for (int s_ = 0; s_ < 4; s_++) {                                         \
            const int c_ = ((tid & 3) + 4 * s_) * 4;                             \
            CP_ASYNC16(kb + (r_ * FKP + c_) * 4,                                 \
                       kptr + (size_t)((kt) * 64 + r_) * C3 + c_);               \
        }                                                                        \
        _Pragma("unroll")                                                        \
        for (int s_ = 0; s_ < 2; s_++) {                                         \
            const int ch_ = ((tid & 3) + 4 * s_) * 8;                            \
            CP_ASYNC16(vb + r_ * (FVP * 2) + ch_ * 2,                            \
                       vptr + (size_t)((kt) * 64 + r_) * NST + ch_);             \
        }                                                                        \
    } while (0)

    PREFETCH_KV(0, 0); CP_COMMIT();
    PREFETCH_KV(1, 1); CP_COMMIT();

    float oacc[8][4];
    #pragma unroll
    for (int nb = 0; nb < 8; nb++)
        #pragma unroll
        for (int r = 0; r < 4; r++) oacc[nb][r] = 0.0f;
    float m0 = -1e30f, m1 = -1e30f, l0 = 0.0f, l1 = 0.0f;

    const int pr = wid * 16 + gid;
    const int grow0 = qb * 128 + pr;
    const int grow1 = grow0 + 8;

    const int nkt = 2 * qb + 2;
    for (int kt = 0; kt < nkt; kt++) {
        const int st = kt & 1;
        CP_WAIT1();
        __syncthreads();      // stage kt visible to all

        const float* Ks = sm + KS_OFF + st * KSTG;
        const uint32_t vbase = smb + VH_OFF + st * VSTG;

        // S = Q K^T (tf32)
        float sacc[8][4];
        #pragma unroll
        for (int nb = 0; nb < 8; nb++)
            #pragma unroll
            for (int r = 0; r < 4; r++) sacc[nb][r] = 0.0f;

        #pragma unroll
        for (int ks = 0; ks < 8; ks++) {
            uint32_t a[4];
            a[0] = __float_as_uint(Qs[pr * FQP + ks * 8 + tig]);
            a[1] = __float_as_uint(Qs[(pr + 8) * FQP + ks * 8 + tig]);
            a[2] = __float_as_uint(Qs[pr * FQP + ks * 8 + tig + 4]);
            a[3] = __float_as_uint(Qs[(pr + 8) * FQP + ks * 8 + tig + 4]);
            #pragma unroll
            for (int nb = 0; nb < 8; nb++) {
                uint32_t bb[2];
                bb[0] = __float_as_uint(Ks[(nb * 8 + gid) * FKP + ks * 8 + tig]);
                bb[1] = __float_as_uint(Ks[(nb * 8 + gid) * FKP + ks * 8 + tig + 4]);
                MMA_TF32(sacc[nb], a, bb);
            }
        }

        // scale (post-mma), then causal mask
        #pragma unroll
        for (int nb = 0; nb < 8; nb++) {
            sacc[nb][0] *= qls; sacc[nb][1] *= qls;
            sacc[nb][2] *= qls; sacc[nb][3] *= qls;
        }
        if (kt >= 2 * qb) {
            #pragma unroll
            for (int nb = 0; nb < 8; nb++) {
                const int c = kt * 64 + nb * 8 + 2 * tig;
                if (c > grow0)     sacc[nb][0] = -1e30f;
                if (c + 1 > grow0) sacc[nb][1] = -1e30f;
                if (c > grow1)     sacc[nb][2] = -1e30f;
                if (c + 1 > grow1) sacc[nb][3] = -1e30f;
            }
        }

        // online softmax (log2 domain)
        float mx0 = -1e30f, mx1 = -1e30f;
        #pragma unroll
        for (int nb = 0; nb < 8; nb++) {
            mx0 = fmaxf(mx0, fmaxf(sacc[nb][0], sacc[nb][1]));
            mx1 = fmaxf(mx1, fmaxf(sacc[nb][2], sacc[nb][3]));
        }
        mx0 = fmaxf(mx0, __shfl_xor_sync(0xffffffffu, mx0, 1));
        mx0 = fmaxf(mx0, __shfl_xor_sync(0xffffffffu, mx0, 2));
        mx1 = fmaxf(mx1, __shfl_xor_sync(0xffffffffu, mx1, 1));
        mx1 = fmaxf(mx1, __shfl_xor_sync(0xffffffffu, mx1, 2));
        const float mn0 = fmaxf(m0, mx0), mn1 = fmaxf(m1, mx1);
        const float al0 = exp2f(m0 - mn0), al1 = exp2f(m1 - mn1);
        float sum0 = 0.0f, sum1 = 0.0f;
        #pragma unroll
        for (int nb = 0; nb < 8; nb++) {
            sacc[nb][0] = exp2f(sacc[nb][0] - mn0);
            sacc[nb][1] = exp2f(sacc[nb][1] - mn0);
            sacc[nb][2] = exp2f(sacc[nb][2] - mn1);
            sacc[nb][3] = exp2f(sacc[nb][3] - mn1);
            sum0 += sacc[nb][0] + sacc[nb][1];
            sum1 += sacc[nb][2] + sacc[nb][3];
        }
        sum0 += __shfl_xor_sync(0xffffffffu, sum0, 1);
        sum0 += __shfl_xor_sync(0xffffffffu, sum0, 2);
        sum1 += __shfl_xor_sync(0xffffffffu, sum1, 1);
        sum1 += __shfl_xor_sync(0xffffffffu, sum1, 2);
        l0 = l0 * al0 + sum0;
        l1 = l1 * al1 + sum1;
        m0 = mn0; m1 = mn1;
        #pragma unroll
        for (int nb = 0; nb < 8; nb++) {
            oacc[nb][0] *= al0; oacc[nb][1] *= al0;
            oacc[nb][2] *= al1; oacc[nb][3] *= al1;
        }

        // PV: fp16 m16n8k16. P a-frags straight from sacc registers;
        // V b-frags via ldmatrix.x4.trans from [k][n] fp16 smem.
        const int l16 = lane & 15;
        const int chalf = (lane >> 4) << 3;
        #pragma unroll
        for (int nbp = 0; nbp < 4; nbp++) {
            uint32_t pa[4];
            pa[0] = pack_h2(sacc[2 * nbp][0],     sacc[2 * nbp][1]);
            pa[1] = pack_h2(sacc[2 * nbp][2],     sacc[2 * nbp][3]);
            pa[2] = pack_h2(sacc[2 * nbp + 1][0], sacc[2 * nbp + 1][1]);
            pa[3] = pack_h2(sacc[2 * nbp + 1][2], sacc[2 * nbp + 1][3]);
            const int k0 = nbp * 16;
            #pragma unroll
            for (int np = 0; np < 4; np++) {
                const int n0c = np * 16;
                uint32_t b0, b1, b2, b3;
                const uint32_t va =
                    vbase + ((k0 + l16) * FVP + n0c + chalf) * 2;
                LDMX4T(b0, b1, b2, b3, va);
                MMA_F16(oacc[2 * np],     pa, b0, b1);
                MMA_F16(oacc[2 * np + 1], pa, b2, b3);
            }
        }

        __syncthreads();      // all warps done with stage st
        if (kt + 2 < nkt) { PREFETCH_KV(kt + 2, st); }
        CP_COMMIT();
    }

    // Epilogue: normalize, tf32-round, write merged heads
    const float inv0 = 1.0f / l0, inv1 = 1.0f / l1;
    float* orow0 = outp + ((size_t)b * S_ + grow0) * NST + hoff;
    float* orow1 = outp + ((size_t)b * S_ + grow1) * NST + hoff;
    #pragma unroll
    for (int nb = 0; nb < 8; nb++) {
        const int c = nb * 8 + 2 * tig;
        float2 v0 = make_float2(cvt_tf32(oacc[nb][0] * inv0),
                                cvt_tf32(oacc[nb][1] * inv0));
        float2 v1 = make_float2(cvt_tf32(oacc[nb][2] * inv1),
                                cvt_tf32(oacc[nb][3] * inv1));
        *(float2*)(orow0 + c) = v0;
        *(float2*)(orow1 + c) = v1;
    }
}

// ---------------------------------------------------------------------------
extern "C" void kernel_launch(void* const* d_in, const int* in_sizes, int n_in,
                              void* d_out, int out_size)
{
    const float* x   = (const float*)d_in[0];
    const float* w_c = (const float*)d_in[1];
    const float* b_c = (const float*)d_in[2];
    const float* w_p = (const float*)d_in[3];
    const float* b_p = (const float*)d_in[4];
    float* out = (float*)d_out;

    void *qkv_p, *vh_p, *attn_p, *xr_p, *wct_p, *wpt_p;
    cudaGetSymbolAddress(&qkv_p, g_qkv);
    cudaGetSymbolAddress(&vh_p, g_vh);
    cudaGetSymbolAddress(&attn_p, g_attn);
    cudaGetSymbolAddress(&xr_p, g_xr);
    cudaGetSymbolAddress(&wct_p, g_wct);
    cudaGetSymbolAddress(&wpt_p, g_wpt);
    float*  qkv  = (float*)qkv_p;
    __half* vhp  = (__half*)vh_p;
    float*  attn = (float*)attn_p;
    float*  xr   = (float*)xr_p;
    float*  wct  = (float*)wct_p;
    float*  wpt  = (float*)wpt_p;

    static bool attr_done = false;
    if (!attr_done) {
        cudaFuncSetAttribute(gemm_mma_kernel,
                             cudaFuncAttributeMaxDynamicSharedMemorySize, GEMM_SMEM);
        cudaFuncSetAttribute(flash_mma_kernel,
                             cudaFuncAttributeMaxDynamicSharedMemorySize, FLASH_SMEM);
        attr_done = true;
    }

    // 0) tf32-round x; transpose + round weights
    round_tf32_kernel<<<(MROWS * NX_ / 4 + 255) / 256, 256>>>(x, xr, MROWS * NX_ / 4);
    transpose_round_kernel<<<dim3(C3 / 32, NX_ / 32), dim3(32, 8)>>>(w_c, wct, NX_, C3);
    transpose_round_kernel<<<dim3(NST / 32, NX_ / 32), dim3(32, 8)>>>(w_p, wpt, NX_, NST);

    // 1) QKV projection (rounds q/k to tf32, emits v also as fp16)
    gemm_mma_kernel<<<dim3(C3 / GBN, MROWS / GBM), 256, GEMM_SMEM>>>(
        xr, wct, b_c, qkv, vhp, 1, MROWS, C3, NX_);

    // 2) Flash attention (tf32 QK^T + fp16 PV)
    flash_mma_kernel<<<dim3(S_ / 128, NH, B_), 256, FLASH_SMEM>>>(qkv, vhp, attn);

    // 3) Output projection
    gemm_mma_kernel<<<dim3(NST / GBN, MROWS / GBM), 256, GEMM_SMEM>>>(
        attn, wpt, b_p, out, (__half*)nullptr, 0, MROWS, NST, NX_);
}

// round 8
// speedup vs baseline: 5.4184x; 1.4302x over previous
#include <cuda_runtime.h>
#include <math_constants.h>
#include <cuda_fp16.h>
#include <cstdint>

#define B_    2
#define S_    2048
#define NX_   1024
#define NST   1024
#define NH    16
#define HD    64
#define MROWS 4096
#define C3    3072

// Scratch (no allocations allowed)
__device__ __half g_qkvh[MROWS * C3];   // [4096, 3072] q|k|v fp16
__device__ __half g_attnh[MROWS * NST]; // merged heads fp16
__device__ __half g_xh[MROWS * NX_];    // x fp16
__device__ __half g_wcth[C3 * NX_];     // w_c^T fp16
__device__ __half g_wpth[NST * NX_];    // w_p^T fp16

__device__ __forceinline__ uint32_t smem_u32(const void* p) {
    uint32_t a;
    asm("{ .reg .u64 t; cvta.to.shared.u64 t, %1; cvt.u32.u64 %0, t; }"
        : "=r"(a) : "l"(p));
    return a;
}
__device__ __forceinline__ uint32_t pack_h2(float lo, float hi) {
    uint32_t r;
    asm("cvt.rn.f16x2.f32 %0, %1, %2;" : "=r"(r) : "f"(hi), "f"(lo));
    return r;
}
#define CP_ASYNC16(smaddr, gptr) \
    asm volatile("cp.async.cg.shared.global [%0], [%1], 16;" \
                 :: "r"(smaddr), "l"(gptr) : "memory")
#define CP_COMMIT() asm volatile("cp.async.commit_group;" ::: "memory")
#define CP_WAIT1()  asm volatile("cp.async.wait_group 1;" ::: "memory")

#define MMA_F16(acc, a, b0, b1)                                                \
    asm volatile(                                                              \
        "mma.sync.aligned.m16n8k16.row.col.f32.f16.f16.f32 "                   \
        "{%0,%1,%2,%3}, {%4,%5,%6,%7}, {%8,%9}, {%0,%1,%2,%3};"                \
        : "+f"((acc)[0]), "+f"((acc)[1]), "+f"((acc)[2]), "+f"((acc)[3])       \
        : "r"((a)[0]), "r"((a)[1]), "r"((a)[2]), "r"((a)[3]),                  \
          "r"(b0), "r"(b1))

#define LDMX4(r0, r1, r2, r3, addr)                                            \
    asm volatile(                                                              \
        "ldmatrix.sync.aligned.m8n8.x4.shared.b16 {%0,%1,%2,%3}, [%4];"        \
        : "=r"(r0), "=r"(r1), "=r"(r2), "=r"(r3) : "r"(addr))

#define LDMX4T(r0, r1, r2, r3, addr)                                           \
    asm volatile(                                                              \
        "ldmatrix.sync.aligned.m8n8.x4.trans.shared.b16 {%0,%1,%2,%3}, [%4];"  \
        : "=r"(r0), "=r"(r1), "=r"(r2), "=r"(r3) : "r"(addr))

// ---------------------------------------------------------------------------
// Prep: f32 -> fp16 elementwise, and transpose+convert weights
// ---------------------------------------------------------------------------
__global__ __launch_bounds__(256) void round_f16_kernel(
    const float* __restrict__ in, __half* __restrict__ out, int n4)
{
    int i = blockIdx.x * 256 + threadIdx.x;
    if (i < n4) {
        float4 v = ((const float4*)in)[i];
        uint2 o;
        o.x = pack_h2(v.x, v.y);
        o.y = pack_h2(v.z, v.w);
        ((uint2*)out)[i] = o;
    }
}

__global__ __launch_bounds__(256) void transpose_f16_kernel(
    const float* __restrict__ W, __half* __restrict__ WT, int K, int N)
{
    __shared__ float t[32][33];
    const int tx = threadIdx.x, ty = threadIdx.y;
    const int n0 = blockIdx.x * 32, k0 = blockIdx.y * 32;
    #pragma unroll
    for (int i = 0; i < 32; i += 8)
        t[ty + i][tx] = W[(size_t)(k0 + ty + i) * N + n0 + tx];
    __syncthreads();
    #pragma unroll
    for (int i = 0; i < 32; i += 8)
        WT[(size_t)(n0 + ty + i) * K + k0 + tx] = __float2half(t[tx][ty + i]);
}

// ---------------------------------------------------------------------------
// fp16 mma GEMM:  C[M,N] = A[M,K] @ BT[N,K]^T + bias
// BM=128, BN=128, BK=64. 8 warps (2x4), warp tile 64x32.
// 3-stage cp.async, one barrier per chunk. Operand frags via ldmatrix.x4.
// Pitch 72 halves (144 B; ldmatrix rows hit banks 4r mod 32, conflict-free).
// qkv_mode=1: write fp16 to QH only (q|k|v). mode 0: write f32 C + bias.
// ---------------------------------------------------------------------------
#define GBM 128
#define GBN 128
#define GBK 64
#define HP  72
#define TILE_H (128 * HP)                 // halves per tile per stage
#define GEMM_SMEM (6 * TILE_H * 2)        // 110592 B

__global__ __launch_bounds__(256, 2) void gemm_f16_kernel(
    const __half* __restrict__ A, const __half* __restrict__ BT,
    const float* __restrict__ bias, float* __restrict__ C,
    __half* __restrict__ QH, int qkv_mode,
    int M, int N, int K)
{
    extern __shared__ __align__(16) __half smh[];
    const uint32_t smb = smem_u32(smh);

    const int tid = threadIdx.x;
    const int wid = tid >> 5, lane = tid & 31;
    const int gid = lane >> 2, tig = lane & 3;
    const int warp_m = wid & 1, warp_n = wid >> 1;

    const int m0 = blockIdx.y * GBM;
    const int n0 = blockIdx.x * GBN;

    // cp.async mapping: 128 rows x 64 halves per tile; 4 xfers per thread
    const int cr = tid >> 1;
    const int cb = (tid & 1) << 3;         // halves: 0 or 8

    const __half* Ap = A + (size_t)m0 * K;
    const __half* Bp = BT + (size_t)n0 * K;

    const int nchunk = K / GBK;

    // ldmatrix per-lane address components
    const int mrow = lane & 15;            // A: row within m16
    const int kcolA = (lane >> 4) << 3;    // A: k offset 0/8
    const int nrow = ((lane >> 4) << 3) + (lane & 7);   // B: row within n16
    const int kcolB = ((lane >> 3) & 1) << 3;           // B: k offset 0/8

    float acc[4][4][4];
    #pragma unroll
    for (int i = 0; i < 4; i++)
        #pragma unroll
        for (int j = 0; j < 4; j++)
            #pragma unroll
            for (int r = 0; r < 4; r++) acc[i][j][r] = 0.0f;

    #define PREFETCH(kc, st) do {                                               \
        const uint32_t abase = smb + (st) * TILE_H * 2;                         \
        const uint32_t bbase = smb + (3 + (st)) * TILE_H * 2;                   \
        _Pragma("unroll")                                                       \
        for (int s = 0; s < 4; s++) {                                           \
            const int col = cb + s * 16;                                        \
            CP_ASYNC16(abase + (cr * HP + col) * 2,                             \
                       Ap + (size_t)cr * K + (kc) * GBK + col);                 \
            CP_ASYNC16(bbase + (cr * HP + col) * 2,                             \
                       Bp + (size_t)cr * K + (kc) * GBK + col);                 \
        }                                                                       \
    } while (0)

    PREFETCH(0, 0); CP_COMMIT();
    PREFETCH(1, 1); CP_COMMIT();

    for (int kc = 0; kc < nchunk; kc++) {
        const int st = kc % 3;
        CP_WAIT1();
        __syncthreads();
        if (kc + 2 < nchunk) { PREFETCH(kc + 2, (kc + 2) % 3); }
        CP_COMMIT();

        const uint32_t Asb = smb + st * TILE_H * 2;
        const uint32_t Bsb = smb + (3 + st) * TILE_H * 2;

        #pragma unroll
        for (int k0 = 0; k0 < GBK; k0 += 16) {
            uint32_t af[4][4];
            #pragma unroll
            for (int i = 0; i < 4; i++) {
                const uint32_t a =
                    Asb + ((warp_m * 64 + i * 16 + mrow) * HP + k0 + kcolA) * 2;
                LDMX4(af[i][0], af[i][1], af[i][2], af[i][3], a);
            }
            #pragma unroll
            for (int j = 0; j < 2; j++) {
                uint32_t b0, b1, b2, b3;
                const uint32_t a =
                    Bsb + ((warp_n * 32 + j * 16 + nrow) * HP + k0 + kcolB) * 2;
                LDMX4(b0, b1, b2, b3, a);
                #pragma unroll
                for (int i = 0; i < 4; i++) {
                    MMA_F16(acc[i][2 * j],     af[i], b0, b1);
                    MMA_F16(acc[i][2 * j + 1], af[i], b2, b3);
                }
            }
        }
    }

    if (qkv_mode) {
        #pragma unroll
        for (int i = 0; i < 4; i++) {
            const int r0 = m0 + warp_m * 64 + i * 16 + gid;
            #pragma unroll
            for (int j = 0; j < 4; j++) {
                const int col = n0 + warp_n * 32 + j * 8 + 2 * tig;
                const float bx = bias[col], by = bias[col + 1];
                *(uint32_t*)(QH + (size_t)r0 * C3 + col) =
                    pack_h2(acc[i][j][0] + bx, acc[i][j][1] + by);
                *(uint32_t*)(QH + (size_t)(r0 + 8) * C3 + col) =
                    pack_h2(acc[i][j][2] + bx, acc[i][j][3] + by);
            }
        }
    } else {
        #pragma unroll
        for (int i = 0; i < 4; i++) {
            const int r0 = m0 + warp_m * 64 + i * 16 + gid;
            #pragma unroll
            for (int j = 0; j < 4; j++) {
                const int col = n0 + warp_n * 32 + j * 8 + 2 * tig;
                const float bx = bias[col], by = bias[col + 1];
                float2 v0 = make_float2(acc[i][j][0] + bx, acc[i][j][1] + by);
                float2 v1 = make_float2(acc[i][j][2] + bx, acc[i][j][3] + by);
                *(float2*)(C + (size_t)r0 * N + col) = v0;
                *(float2*)(C + (size_t)(r0 + 8) * N + col) = v1;
            }
        }
    }
}

// ---------------------------------------------------------------------------
// Flash attention, all-fp16 operands (f32 accumulate/softmax).
// QK^T: m16n8k16, Q/K frags via ldmatrix.x4 from [row][k] fp16 smem.
// PV:   m16n8k16, P stays in registers (C-frag == A-frag layout),
//       V frags via ldmatrix.x4.trans from [k][n] fp16 smem.
// Smem (halves): Q 128x72 | K 2x 64x72 | V 2x 64x72 = 55296 B.
// ---------------------------------------------------------------------------
#define KOFF 9216                            // halves
#define KVSTG 4608                           // halves per K or V stage
#define VOFF  (KOFF + 2 * KVSTG)
#define FLASH_SMEM ((VOFF + 2 * KVSTG) * 2)  // 55296 B

__global__ __launch_bounds__(256, 2) void flash_f16_kernel(
    const __half* __restrict__ qkvh, __half* __restrict__ attnh)
{
    extern __shared__ __align__(16) __half smh[];
    const uint32_t smb = smem_u32(smh);

    const int qb = (int)gridDim.x - 1 - (int)blockIdx.x;  // heavy first
    const int h  = blockIdx.y;
    const int b  = blockIdx.z;
    const int tid = threadIdx.x;
    const int wid = tid >> 5, lane = tid & 31;
    const int gid = lane >> 2, tig = lane & 3;

    const int hoff = h * HD;
    const __half* qptr = qkvh + (size_t)b * S_ * C3 + (size_t)qb * 128 * C3 + hoff;
    const __half* kptr = qkvh + (size_t)b * S_ * C3 + NST + hoff;
    const __half* vptr = qkvh + (size_t)b * S_ * C3 + 2 * NST + hoff;
    const float qls = 0.125f * 1.4426950408889634f;   // rsqrt(64)*log2(e)

    // Q tile (group 0): 128 rows x 64 halves
    {
        const int r = tid >> 1;
        const int cb = (tid & 1) << 3;
        #pragma unroll
        for (int s = 0; s < 4; s++) {
            const int c = cb + s * 16;
            CP_ASYNC16(smb + (r * HP + c) * 2, qptr + (size_t)r * C3 + c);
        }
        CP_COMMIT();
    }

    #define PREFETCH_KV(kt, st) do {                                            \
        const uint32_t kb = smb + (KOFF + (st) * KVSTG) * 2;                     \
        const uint32_t vb = smb + (VOFF + (st) * KVSTG) * 2;                     \
        const int r_ = tid >> 2;                                                 \
        _Pragma("unroll")                                                        \
        for (int s_ = 0; s_ < 2; s_++) {                                         \
            const int c_ = ((tid & 3) + 4 * s_) * 8;                             \
            CP_ASYNC16(kb + (r_ * HP + c_) * 2,                                  \
                       kptr + (size_t)((kt) * 64 + r_) * C3 + c_);               \
            CP_ASYNC16(vb + (r_ * HP + c_) * 2,                                  \
                       vptr + (size_t)((kt) * 64 + r_) * C3 + c_);               \
        }                                                                        \
    } while (0)

    PREFETCH_KV(0, 0); CP_COMMIT();
    PREFETCH_KV(1, 1); CP_COMMIT();

    float oacc[8][4];
    #pragma unroll
    for (int nb = 0; nb < 8; nb++)
        #pragma unroll
        for (int r = 0; r < 4; r++) oacc[nb][r] = 0.0f;
    float m0 = -1e30f, m1 = -1e30f, l0 = 0.0f, l1 = 0.0f;

    const int pr = wid * 16 + gid;
    const int grow0 = qb * 128 + pr;
    const int grow1 = grow0 + 8;

    // ldmatrix lane components
    const int mrow = lane & 15;
    const int kcolA = (lane >> 4) << 3;
    const int nrow = ((lane >> 4) << 3) + (lane & 7);
    const int kcolB = ((lane >> 3) & 1) << 3;
    const int l16 = lane & 15;
    const int chalf = (lane >> 4) << 3;

    const int nkt = 2 * qb + 2;
    for (int kt = 0; kt < nkt; kt++) {
        const int st = kt & 1;
        CP_WAIT1();
        __syncthreads();

        const uint32_t Ksb = smb + (KOFF + st * KVSTG) * 2;
        const uint32_t vbase = smb + (VOFF + st * KVSTG) * 2;

        // S = Q K^T (fp16 mma, f32 acc)
        float sacc[8][4];
        #pragma unroll
        for (int nb = 0; nb < 8; nb++)
            #pragma unroll
            for (int r = 0; r < 4; r++) sacc[nb][r] = 0.0f;

        #pragma unroll
        for (int k0 = 0; k0 < 64; k0 += 16) {
            uint32_t qa[4];
            LDMX4(qa[0], qa[1], qa[2], qa[3],
                  smb + ((wid * 16 + mrow) * HP + k0 + kcolA) * 2);
            #pragma unroll
            for (int j = 0; j < 4; j++) {
                uint32_t b0, b1, b2, b3;
                LDMX4(b0, b1, b2, b3,
                      Ksb + ((j * 16 + nrow) * HP + k0 + kcolB) * 2);
                MMA_F16(sacc[2 * j],     qa, b0, b1);
                MMA_F16(sacc[2 * j + 1], qa, b2, b3);
            }
        }

        // scale (post-mma), causal mask on diagonal-crossing tiles
        #pragma unroll
        for (int nb = 0; nb < 8; nb++) {
            sacc[nb][0] *= qls; sacc[nb][1] *= qls;
            sacc[nb][2] *= qls; sacc[nb][3] *= qls;
        }
        if (kt >= 2 * qb) {
            #pragma unroll
            for (int nb = 0; nb < 8; nb++) {
                const int c = kt * 64 + nb * 8 + 2 * tig;
                if (c > grow0)     sacc[nb][0] = -1e30f;
                if (c + 1 > grow0) sacc[nb][1] = -1e30f;
                if (c > grow1)     sacc[nb][2] = -1e30f;
                if (c + 1 > grow1) sacc[nb][3] = -1e30f;
            }
        }

        // online softmax (log2 domain)
        float mx0 = -1e30f, mx1 = -1e30f;
        #pragma unroll
        for (int nb = 0; nb < 8; nb++) {
            mx0 = fmaxf(mx0, fmaxf(sacc[nb][0], sacc[nb][1]));
            mx1 = fmaxf(mx1, fmaxf(sacc[nb][2], sacc[nb][3]));
        }
        mx0 = fmaxf(mx0, __shfl_xor_sync(0xffffffffu, mx0, 1));
        mx0 = fmaxf(mx0, __shfl_xor_sync(0xffffffffu, mx0, 2));
        mx1 = fmaxf(mx1, __shfl_xor_sync(0xffffffffu, mx1, 1));
        mx1 = fmaxf(mx1, __shfl_xor_sync(0xffffffffu, mx1, 2));
        const float mn0 = fmaxf(m0, mx0), mn1 = fmaxf(m1, mx1);
        const float al0 = exp2f(m0 - mn0), al1 = exp2f(m1 - mn1);
        float sum0 = 0.0f, sum1 = 0.0f;
        #pragma unroll
        for (int nb = 0; nb < 8; nb++) {
            sacc[nb][0] = exp2f(sacc[nb][0] - mn0);
            sacc[nb][1] = exp2f(sacc[nb][1] - mn0);
            sacc[nb][2] = exp2f(sacc[nb][2] - mn1);
            sacc[nb][3] = exp2f(sacc[nb][3] - mn1);
            sum0 += sacc[nb][0] + sacc[nb][1];
            sum1 += sacc[nb][2] + sacc[nb][3];
        }
        sum0 += __shfl_xor_sync(0xffffffffu, sum0, 1);
        sum0 += __shfl_xor_sync(0xffffffffu, sum0, 2);
        sum1 += __shfl_xor_sync(0xffffffffu, sum1, 1);
        sum1 += __shfl_xor_sync(0xffffffffu, sum1, 2);
        l0 = l0 * al0 + sum0;
        l1 = l1 * al1 + sum1;
        m0 = mn0; m1 = mn1;
        #pragma unroll
        for (int nb = 0; nb < 8; nb++) {
            oacc[nb][0] *= al0; oacc[nb][1] *= al0;
            oacc[nb][2] *= al1; oacc[nb][3] *= al1;
        }

        // PV: P from registers, V via ldmatrix.x4.trans
        #pragma unroll
        for (int nbp = 0; nbp < 4; nbp++) {
            uint32_t pa[4];
            pa[0] = pack_h2(sacc[2 * nbp][0],     sacc[2 * nbp][1]);
            pa[1] = pack_h2(sacc[2 * nbp][2],     sacc[2 * nbp][3]);
            pa[2] = pack_h2(sacc[2 * nbp + 1][0], sacc[2 * nbp + 1][1]);
            pa[3] = pack_h2(sacc[2 * nbp + 1][2], sacc[2 * nbp + 1][3]);
            const int k0 = nbp * 16;
            #pragma unroll
            for (int np = 0; np < 4; np++) {
                const int n0c = np * 16;
                uint32_t b0, b1, b2, b3;
                const uint32_t va =
                    vbase + ((k0 + l16) * HP + n0c + chalf) * 2;
                LDMX4T(b0, b1, b2, b3, va);
                MMA_F16(oacc[2 * np],     pa, b0, b1);
                MMA_F16(oacc[2 * np + 1], pa, b2, b3);
            }
        }

        __syncthreads();
        if (kt + 2 < nkt) { PREFETCH_KV(kt + 2, st); }
        CP_COMMIT();
    }

    // Epilogue: normalize, write fp16 merged heads
    const float inv0 = 1.0f / l0, inv1 = 1.0f / l1;
    __half* orow0 = attnh + ((size_t)b * S_ + grow0) * NST + hoff;
    __half* orow1 = attnh + ((size_t)b * S_ + grow1) * NST + hoff;
    #pragma unroll
    for (int nb = 0; nb < 8; nb++) {
        const int c = nb * 8 + 2 * tig;
        *(uint32_t*)(orow0 + c) = pack_h2(oacc[nb][0] * inv0, oacc[nb][1] * inv0);
        *(uint32_t*)(orow1 + c) = pack_h2(oacc[nb][2] * inv1, oacc[nb][3] * inv1);
    }
}

// ---------------------------------------------------------------------------
extern "C" void kernel_launch(void* const* d_in, const int* in_sizes, int n_in,
                              void* d_out, int out_size)
{
    const float* x   = (const float*)d_in[0];
    const float* w_c = (const float*)d_in[1];
    const float* b_c = (const float*)d_in[2];
    const float* w_p = (const float*)d_in[3];
    const float* b_p = (const float*)d_in[4];
    float* out = (float*)d_out;

    void *qkvh_p, *attnh_p, *xh_p, *wcth_p, *wpth_p;
    cudaGetSymbolAddress(&qkvh_p, g_qkvh);
    cudaGetSymbolAddress(&attnh_p, g_attnh);
    cudaGetSymbolAddress(&xh_p, g_xh);
    cudaGetSymbolAddress(&wcth_p, g_wcth);
    cudaGetSymbolAddress(&wpth_p, g_wpth);
    __half* qkvh  = (__half*)qkvh_p;
    __half* attnh = (__half*)attnh_p;
    __half* xh    = (__half*)xh_p;
    __half* wcth  = (__half*)wcth_p;
    __half* wpth  = (__half*)wpth_p;

    static bool attr_done = false;
    if (!attr_done) {
        cudaFuncSetAttribute(gemm_f16_kernel,
                             cudaFuncAttributeMaxDynamicSharedMemorySize, GEMM_SMEM);
        cudaFuncSetAttribute(flash_f16_kernel,
                             cudaFuncAttributeMaxDynamicSharedMemorySize, FLASH_SMEM);
        attr_done = true;
    }

    // 0) Convert x and weights to fp16 (weights transposed)
    round_f16_kernel<<<(MROWS * NX_ / 4 + 255) / 256, 256>>>(x, xh, MROWS * NX_ / 4);
    transpose_f16_kernel<<<dim3(C3 / 32, NX_ / 32), dim3(32, 8)>>>(w_c, wcth, NX_, C3);
    transpose_f16_kernel<<<dim3(NST / 32, NX_ / 32), dim3(32, 8)>>>(w_p, wpth, NX_, NST);

    // 1) QKV projection -> fp16 q|k|v
    gemm_f16_kernel<<<dim3(C3 / GBN, MROWS / GBM), 256, GEMM_SMEM>>>(
        xh, wcth, b_c, nullptr, qkvh, 1, MROWS, C3, NX_);

    // 2) Flash attention (fp16 mma) -> fp16 merged heads
    flash_f16_kernel<<<dim3(S_ / 128, NH, B_), 256, FLASH_SMEM>>>(qkvh, attnh);

    // 3) Output projection -> f32 out
    gemm_f16_kernel<<<dim3(NST / GBN, MROWS / GBM), 256, GEMM_SMEM>>>(
        attnh, wpth, b_p, out, nullptr, 0, MROWS, NST, NX_);
}

// round 9
// speedup vs baseline: 5.5063x; 1.0162x over previous
#include <cuda_runtime.h>
#include <math_constants.h>
#include <cuda_fp16.h>
#include <cstdint>

#define B_    2
#define S_    2048
#define NX_   1024
#define NST   1024
#define NH    16
#define HD    64
#define MROWS 4096
#define C3    3072

// Scratch (no allocations allowed)
__device__ __half g_qkvh[MROWS * C3];   // [4096, 3072] q|k|v fp16
__device__ __half g_attnh[MROWS * NST]; // merged heads fp16
__device__ __half g_xh[MROWS * NX_];    // x fp16
__device__ __half g_wcth[C3 * NX_];     // w_c^T fp16
__device__ __half g_wpth[NST * NX_];    // w_p^T fp16

__device__ __forceinline__ uint32_t smem_u32(const void* p) {
    uint32_t a;
    asm("{ .reg .u64 t; cvta.to.shared.u64 t, %1; cvt.u32.u64 %0, t; }"
        : "=r"(a) : "l"(p));
    return a;
}
__device__ __forceinline__ uint32_t pack_h2(float lo, float hi) {
    uint32_t r;
    asm("cvt.rn.f16x2.f32 %0, %1, %2;" : "=r"(r) : "f"(hi), "f"(lo));
    return r;
}
#define CP_ASYNC16(smaddr, gptr) \
    asm volatile("cp.async.cg.shared.global [%0], [%1], 16;" \
                 :: "r"(smaddr), "l"(gptr) : "memory")
#define CP_COMMIT() asm volatile("cp.async.commit_group;" ::: "memory")
#define CP_WAIT1()  asm volatile("cp.async.wait_group 1;" ::: "memory")

#define MMA_F16(acc, a, b0, b1)                                                \
    asm volatile(                                                              \
        "mma.sync.aligned.m16n8k16.row.col.f32.f16.f16.f32 "                   \
        "{%0,%1,%2,%3}, {%4,%5,%6,%7}, {%8,%9}, {%0,%1,%2,%3};"                \
        : "+f"((acc)[0]), "+f"((acc)[1]), "+f"((acc)[2]), "+f"((acc)[3])       \
        : "r"((a)[0]), "r"((a)[1]), "r"((a)[2]), "r"((a)[3]),                  \
          "r"(b0), "r"(b1))

#define LDMX4(r0, r1, r2, r3, addr)                                            \
    asm volatile(                                                              \
        "ldmatrix.sync.aligned.m8n8.x4.shared.b16 {%0,%1,%2,%3}, [%4];"        \
        : "=r"(r0), "=r"(r1), "=r"(r2), "=r"(r3) : "r"(addr))

#define LDMX4T(r0, r1, r2, r3, addr)                                           \
    asm volatile(                                                              \
        "ldmatrix.sync.aligned.m8n8.x4.trans.shared.b16 {%0,%1,%2,%3}, [%4];"  \
        : "=r"(r0), "=r"(r1), "=r"(r2), "=r"(r3) : "r"(addr))

// ---------------------------------------------------------------------------
// Prep: f32 -> fp16 elementwise, and transpose+convert weights
// ---------------------------------------------------------------------------
__global__ __launch_bounds__(256) void round_f16_kernel(
    const float* __restrict__ in, __half* __restrict__ out, int n4)
{
    int i = blockIdx.x * 256 + threadIdx.x;
    if (i < n4) {
        float4 v = ((const float4*)in)[i];
        uint2 o;
        o.x = pack_h2(v.x, v.y);
        o.y = pack_h2(v.z, v.w);
        ((uint2*)out)[i] = o;
    }
}

__global__ __launch_bounds__(256) void transpose_f16_kernel(
    const float* __restrict__ W, __half* __restrict__ WT, int K, int N)
{
    __shared__ float t[32][33];
    const int tx = threadIdx.x, ty = threadIdx.y;
    const int n0 = blockIdx.x * 32, k0 = blockIdx.y * 32;
    #pragma unroll
    for (int i = 0; i < 32; i += 8)
        t[ty + i][tx] = W[(size_t)(k0 + ty + i) * N + n0 + tx];
    __syncthreads();
    #pragma unroll
    for (int i = 0; i < 32; i += 8)
        WT[(size_t)(n0 + ty + i) * K + k0 + tx] = __float2half(t[tx][ty + i]);
}

// ---------------------------------------------------------------------------
// fp16 mma GEMM:  C[M,N] = A[M,K] @ BT[N,K]^T + bias
// BM=128, BN=128, BK=64. 8 warps (2x4), warp tile 64x32.
// 3-stage cp.async, one barrier per chunk. Fragments PING-PONG double-
// buffered at k16 granularity: group g+1's ldmatrix issue while group g's
// MMAs execute, hiding the ~30cyc LDSM latency that stalled R8.
// qkv_mode=1: write fp16 to QH only (q|k|v). mode 0: write f32 C + bias.
// ---------------------------------------------------------------------------
#define GBM 128
#define GBN 128
#define GBK 64
#define HP  72
#define TILE_H (128 * HP)                 // halves per tile per stage
#define GEMM_SMEM (6 * TILE_H * 2)        // 110592 B

__global__ __launch_bounds__(256, 2) void gemm_f16_kernel(
    const __half* __restrict__ A, const __half* __restrict__ BT,
    const float* __restrict__ bias, float* __restrict__ C,
    __half* __restrict__ QH, int qkv_mode,
    int M, int N, int K)
{
    extern __shared__ __align__(16) __half smh[];
    const uint32_t smb = smem_u32(smh);

    const int tid = threadIdx.x;
    const int wid = tid >> 5, lane = tid & 31;
    const int gid = lane >> 2, tig = lane & 3;
    const int warp_m = wid & 1, warp_n = wid >> 1;

    const int m0 = blockIdx.y * GBM;
    const int n0 = blockIdx.x * GBN;

    // cp.async mapping: 128 rows x 64 halves per tile; 4 xfers per thread
    const int cr = tid >> 1;
    const int cb = (tid & 1) << 3;         // halves: 0 or 8

    const __half* Ap = A + (size_t)m0 * K;
    const __half* Bp = BT + (size_t)n0 * K;

    const int nchunk = K / GBK;

    // ldmatrix per-lane address components
    const int mrow = lane & 15;
    const int kcolA = (lane >> 4) << 3;
    const int nrow = ((lane >> 4) << 3) + (lane & 7);
    const int kcolB = ((lane >> 3) & 1) << 3;

    float acc[4][4][4];
    #pragma unroll
    for (int i = 0; i < 4; i++)
        #pragma unroll
        for (int j = 0; j < 4; j++)
            #pragma unroll
            for (int r = 0; r < 4; r++) acc[i][j][r] = 0.0f;

    #define PREFETCH(kc, st) do {                                               \
        const uint32_t abase = smb + (st) * TILE_H * 2;                         \
        const uint32_t bbase = smb + (3 + (st)) * TILE_H * 2;                   \
        _Pragma("unroll")                                                       \
        for (int s = 0; s < 4; s++) {                                           \
            const int col = cb + s * 16;                                        \
            CP_ASYNC16(abase + (cr * HP + col) * 2,                             \
                       Ap + (size_t)cr * K + (kc) * GBK + col);                 \
            CP_ASYNC16(bbase + (cr * HP + col) * 2,                             \
                       Bp + (size_t)cr * K + (kc) * GBK + col);                 \
        }                                                                       \
    } while (0)

    PREFETCH(0, 0); CP_COMMIT();
    PREFETCH(1, 1); CP_COMMIT();

    uint32_t af[2][4][4], bf[2][2][4];

    #define LOAD_FRAGS(buf, Asb_, Bsb_, k0_) do {                               \
        _Pragma("unroll")                                                       \
        for (int i = 0; i < 4; i++) {                                           \
            const uint32_t a_ =                                                 \
                (Asb_) + ((warp_m * 64 + i * 16 + mrow) * HP + (k0_) + kcolA) * 2; \
            LDMX4(af[buf][i][0], af[buf][i][1], af[buf][i][2], af[buf][i][3], a_); \
        }                                                                       \
        _Pragma("unroll")                                                       \
        for (int j = 0; j < 2; j++) {                                           \
            const uint32_t b_ =                                                 \
                (Bsb_) + ((warp_n * 32 + j * 16 + nrow) * HP + (k0_) + kcolB) * 2; \
            LDMX4(bf[buf][j][0], bf[buf][j][1], bf[buf][j][2], bf[buf][j][3], b_); \
        }                                                                       \
    } while (0)

    #define MMA_GROUP(buf) do {                                                 \
        _Pragma("unroll")                                                       \
        for (int j = 0; j < 2; j++)                                             \
            _Pragma("unroll")                                                   \
            for (int i = 0; i < 4; i++) {                                       \
                MMA_F16(acc[i][2 * j],     af[buf][i], bf[buf][j][0], bf[buf][j][1]); \
                MMA_F16(acc[i][2 * j + 1], af[buf][i], bf[buf][j][2], bf[buf][j][3]); \
            }                                                                   \
    } while (0)

    for (int kc = 0; kc < nchunk; kc++) {
        const int st = kc % 3;
        CP_WAIT1();
        __syncthreads();

        const uint32_t Asb = smb + st * TILE_H * 2;
        const uint32_t Bsb = smb + (3 + st) * TILE_H * 2;

        // Load group 0 fragments FIRST, then prefetch (keeps LSU free for LDSM)
        LOAD_FRAGS(0, Asb, Bsb, 0);
        if (kc + 2 < nchunk) { PREFETCH(kc + 2, (kc + 2) % 3); }
        CP_COMMIT();

        #pragma unroll
        for (int g = 0; g < 4; g++) {
            if (g < 3) LOAD_FRAGS((g + 1) & 1, Asb, Bsb, (g + 1) * 16);
            MMA_GROUP(g & 1);
        }
    }

    if (qkv_mode) {
        #pragma unroll
        for (int i = 0; i < 4; i++) {
            const int r0 = m0 + warp_m * 64 + i * 16 + gid;
            #pragma unroll
            for (int j = 0; j < 4; j++) {
                const int col = n0 + warp_n * 32 + j * 8 + 2 * tig;
                const float bx = bias[col], by = bias[col + 1];
                *(uint32_t*)(QH + (size_t)r0 * C3 + col) =
                    pack_h2(acc[i][j][0] + bx, acc[i][j][1] + by);
                *(uint32_t*)(QH + (size_t)(r0 + 8) * C3 + col) =
                    pack_h2(acc[i][j][2] + bx, acc[i][j][3] + by);
            }
        }
    } else {
        #pragma unroll
        for (int i = 0; i < 4; i++) {
            const int r0 = m0 + warp_m * 64 + i * 16 + gid;
            #pragma unroll
            for (int j = 0; j < 4; j++) {
                const int col = n0 + warp_n * 32 + j * 8 + 2 * tig;
                const float bx = bias[col], by = bias[col + 1];
                float2 v0 = make_float2(acc[i][j][0] + bx, acc[i][j][1] + by);
                float2 v1 = make_float2(acc[i][j][2] + bx, acc[i][j][3] + by);
                *(float2*)(C + (size_t)r0 * N + col) = v0;
                *(float2*)(C + (size_t)(r0 + 8) * N + col) = v1;
            }
        }
    }
}

// ---------------------------------------------------------------------------
// Flash attention, all-fp16 operands (f32 accumulate/softmax) — as R8.
// ---------------------------------------------------------------------------
#define KOFF 9216                            // halves
#define KVSTG 4608                           // halves per K or V stage
#define VOFF  (KOFF + 2 * KVSTG)
#define FLASH_SMEM ((VOFF + 2 * KVSTG) * 2)  // 55296 B

__global__ __launch_bounds__(256, 2) void flash_f16_kernel(
    const __half* __restrict__ qkvh, __half* __restrict__ attnh)
{
    extern __shared__ __align__(16) __half smh[];
    const uint32_t smb = smem_u32(smh);

    const int qb = (int)gridDim.x - 1 - (int)blockIdx.x;  // heavy first
    const int h  = blockIdx.y;
    const int b  = blockIdx.z;
    const int tid = threadIdx.x;
    const int wid = tid >> 5, lane = tid & 31;
    const int gid = lane >> 2, tig = lane & 3;

    const int hoff = h * HD;
    const __half* qptr = qkvh + (size_t)b * S_ * C3 + (size_t)qb * 128 * C3 + hoff;
    const __half* kptr = qkvh + (size_t)b * S_ * C3 + NST + hoff;
    const __half* vptr = qkvh + (size_t)b * S_ * C3 + 2 * NST + hoff;
    const float qls = 0.125f * 1.4426950408889634f;   // rsqrt(64)*log2(e)

    // Q tile (group 0): 128 rows x 64 halves
    {
        const int r = tid >> 1;
        const int cb = (tid & 1) << 3;
        #pragma unroll
        for (int s = 0; s < 4; s++) {
            const int c = cb + s * 16;
            CP_ASYNC16(smb + (r * HP + c) * 2, qptr + (size_t)r * C3 + c);
        }
        CP_COMMIT();
    }

    #define PREFETCH_KV(kt, st) do {                                            \
        const uint32_t kb = smb + (KOFF + (st) * KVSTG) * 2;                     \
        const uint32_t vb = smb + (VOFF + (st) * KVSTG) * 2;                     \
        const int r_ = tid >> 2;                                                 \
        _Pragma("unroll")                                                        \
        for (int s_ = 0; s_ < 2; s_++) {                                         \
            const int c_ = ((tid & 3) + 4 * s_) * 8;                             \
            CP_ASYNC16(kb + (r_ * HP + c_) * 2,                                  \
                       kptr + (size_t)((kt) * 64 + r_) * C3 + c_);               \
            CP_ASYNC16(vb + (r_ * HP + c_) * 2,                                  \
                       vptr + (size_t)((kt) * 64 + r_) * C3 + c_);               \
        }                                                                        \
    } while (0)

    PREFETCH_KV(0, 0); CP_COMMIT();
    PREFETCH_KV(1, 1); CP_COMMIT();

    float oacc[8][4];
    #pragma unroll
    for (int nb = 0; nb < 8; nb++)
        #pragma unroll
        for (int r = 0; r < 4; r++) oacc[nb][r] = 0.0f;
    float m0 = -1e30f, m1 = -1e30f, l0 = 0.0f, l1 = 0.0f;

    const int pr = wid * 16 + gid;
    const int grow0 = qb * 128 + pr;
    const int grow1 = grow0 + 8;

    const int mrow = lane & 15;
    const int kcolA = (lane >> 4) << 3;
    const int nrow = ((lane >> 4) << 3) + (lane & 7);
    const int kcolB = ((lane >> 3) & 1) << 3;
    const int l16 = lane & 15;
    const int chalf = (lane >> 4) << 3;

    const int nkt = 2 * qb + 2;
    for (int kt = 0; kt < nkt; kt++) {
        const int st = kt & 1;
        CP_WAIT1();
        __syncthreads();

        const uint32_t Ksb = smb + (KOFF + st * KVSTG) * 2;
        const uint32_t vbase = smb + (VOFF + st * KVSTG) * 2;

        // S = Q K^T (fp16 mma, f32 acc)
        float sacc[8][4];
        #pragma unroll
        for (int nb = 0; nb < 8; nb++)
            #pragma unroll
            for (int r = 0; r < 4; r++) sacc[nb][r] = 0.0f;

        #pragma unroll
        for (int k0 = 0; k0 < 64; k0 += 16) {
            uint32_t qa[4];
            LDMX4(qa[0], qa[1], qa[2], qa[3],
                  smb + ((wid * 16 + mrow) * HP + k0 + kcolA) * 2);
            #pragma unroll
            for (int j = 0; j < 4; j++) {
                uint32_t b0, b1, b2, b3;
                LDMX4(b0, b1, b2, b3,
                      Ksb + ((j * 16 + nrow) * HP + k0 + kcolB) * 2);
                MMA_F16(sacc[2 * j],     qa, b0, b1);
                MMA_F16(sacc[2 * j + 1], qa, b2, b3);
            }
        }

        #pragma unroll
        for (int nb = 0; nb < 8; nb++) {
            sacc[nb][0] *= qls; sacc[nb][1] *= qls;
            sacc[nb][2] *= qls; sacc[nb][3] *= qls;
        }
        if (kt >= 2 * qb) {
            #pragma unroll
            for (int nb = 0; nb < 8; nb++) {
                const int c = kt * 64 + nb * 8 + 2 * tig;
                if (c > grow0)     sacc[nb][0] = -1e30f;
                if (c + 1 > grow0) sacc[nb][1] = -1e30f;
                if (c > grow1)     sacc[nb][2] = -1e30f;
                if (c + 1 > grow1) sacc[nb][3] = -1e30f;
            }
        }

        float mx0 = -1e30f, mx1 = -1e30f;
        #pragma unroll
        for (int nb = 0; nb < 8; nb++) {
            mx0 = fmaxf(mx0, fmaxf(sacc[nb][0], sacc[nb][1]));
            mx1 = fmaxf(mx1, fmaxf(sacc[nb][2], sacc[nb][3]));
        }
        mx0 = fmaxf(mx0, __shfl_xor_sync(0xffffffffu, mx0, 1));
        mx0 = fmaxf(mx0, __shfl_xor_sync(0xffffffffu, mx0, 2));
        mx1 = fmaxf(mx1, __shfl_xor_sync(0xffffffffu, mx1, 1));
        mx1 = fmaxf(mx1, __shfl_xor_sync(0xffffffffu, mx1, 2));
        const float mn0 = fmaxf(m0, mx0), mn1 = fmaxf(m1, mx1);
        const float al0 = exp2f(m0 - mn0), al1 = exp2f(m1 - mn1);
        float sum0 = 0.0f, sum1 = 0.0f;
        #pragma unroll
        for (int nb = 0; nb < 8; nb++) {
            sacc[nb][0] = exp2f(sacc[nb][0] - mn0);
            sacc[nb][1] = exp2f(sacc[nb][1] - mn0);
            sacc[nb][2] = exp2f(sacc[nb][2] - mn1);
            sacc[nb][3] = exp2f(sacc[nb][3] - mn1);
            sum0 += sacc[nb][0] + sacc[nb][1];
            sum1 += sacc[nb][2] + sacc[nb][3];
        }
        sum0 += __shfl_xor_sync(0xffffffffu, sum0, 1);
        sum0 += __shfl_xor_sync(0xffffffffu, sum0, 2);
        sum1 += __shfl_xor_sync(0xffffffffu, sum1, 1);
        sum1 += __shfl_xor_sync(0xffffffffu, sum1, 2);
        l0 = l0 * al0 + sum0;
        l1 = l1 * al1 + sum1;
        m0 = mn0; m1 = mn1;
        #pragma unroll
        for (int nb = 0; nb < 8; nb++) {
            oacc[nb][0] *= al0; oacc[nb][1] *= al0;
            oacc[nb][2] *= al1; oacc[nb][3] *= al1;
        }

        #pragma unroll
        for (int nbp = 0; nbp < 4; nbp++) {
            uint32_t pa[4];
            pa[0] = pack_h2(sacc[2 * nbp][0],     sacc[2 * nbp][1]);
            pa[1] = pack_h2(sacc[2 * nbp][2],     sacc[2 * nbp][3]);
            pa[2] = pack_h2(sacc[2 * nbp + 1][0], sacc[2 * nbp + 1][1]);
            pa[3] = pack_h2(sacc[2 * nbp + 1][2], sacc[2 * nbp + 1][3]);
            const int k0 = nbp * 16;
            #pragma unroll
            for (int np = 0; np < 4; np++) {
                const int n0c = np * 16;
                uint32_t b0, b1, b2, b3;
                const uint32_t va =
                    vbase + ((k0 + l16) * HP + n0c + chalf) * 2;
                LDMX4T(b0, b1, b2, b3, va);
                MMA_F16(oacc[2 * np],     pa, b0, b1);
                MMA_F16(oacc[2 * np + 1], pa, b2, b3);
            }
        }

        __syncthreads();
        if (kt + 2 < nkt) { PREFETCH_KV(kt + 2, st); }
        CP_COMMIT();
    }

    const float inv0 = 1.0f / l0, inv1 = 1.0f / l1;
    __half* orow0 = attnh + ((size_t)b * S_ + grow0) * NST + hoff;
    __half* orow1 = attnh + ((size_t)b * S_ + grow1) * NST + hoff;
    #pragma unroll
    for (int nb = 0; nb < 8; nb++) {
        const int c = nb * 8 + 2 * tig;
        *(uint32_t*)(orow0 + c) = pack_h2(oacc[nb][0] * inv0, oacc[nb][1] * inv0);
        *(uint32_t*)(orow1 + c) = pack_h2(oacc[nb][2] * inv1, oacc[nb][3] * inv1);
    }
}

// ---------------------------------------------------------------------------
extern "C" void kernel_launch(void* const* d_in, const int* in_sizes, int n_in,
                              void* d_out, int out_size)
{
    const float* x   = (const float*)d_in[0];
    const float* w_c = (const float*)d_in[1];
    const float* b_c = (const float*)d_in[2];
    const float* w_p = (const float*)d_in[3];
    const float* b_p = (const float*)d_in[4];
    float* out = (float*)d_out;

    void *qkvh_p, *attnh_p, *xh_p, *wcth_p, *wpth_p;
    cudaGetSymbolAddress(&qkvh_p, g_qkvh);
    cudaGetSymbolAddress(&attnh_p, g_attnh);
    cudaGetSymbolAddress(&xh_p, g_xh);
    cudaGetSymbolAddress(&wcth_p, g_wcth);
    cudaGetSymbolAddress(&wpth_p, g_wpth);
    __half* qkvh  = (__half*)qkvh_p;
    __half* attnh = (__half*)attnh_p;
    __half* xh    = (__half*)xh_p;
    __half* wcth  = (__half*)wcth_p;
    __half* wpth  = (__half*)wpth_p;

    static bool attr_done = false;
    if (!attr_done) {
        cudaFuncSetAttribute(gemm_f16_kernel,
                             cudaFuncAttributeMaxDynamicSharedMemorySize, GEMM_SMEM);
        cudaFuncSetAttribute(flash_f16_kernel,
                             cudaFuncAttributeMaxDynamicSharedMemorySize, FLASH_SMEM);
        attr_done = true;
    }

    // 0) Convert x and weights to fp16 (weights transposed)
    round_f16_kernel<<<(MROWS * NX_ / 4 + 255) / 256, 256>>>(x, xh, MROWS * NX_ / 4);
    transpose_f16_kernel<<<dim3(C3 / 32, NX_ / 32), dim3(32, 8)>>>(w_c, wcth, NX_, C3);
    transpose_f16_kernel<<<dim3(NST / 32, NX_ / 32), dim3(32, 8)>>>(w_p, wpth, NX_, NST);

    // 1) QKV projection -> fp16 q|k|v
    gemm_f16_kernel<<<dim3(C3 / GBN, MROWS / GBM), 256, GEMM_SMEM>>>(
        xh, wcth, b_c, nullptr, qkvh, 1, MROWS, C3, NX_);

    // 2) Flash attention (fp16 mma) -> fp16 merged heads
    flash_f16_kernel<<<dim3(S_ / 128, NH, B_), 256, FLASH_SMEM>>>(qkvh, attnh);

    // 3) Output projection -> f32 out
    gemm_f16_kernel<<<dim3(NST / GBN, MROWS / GBM), 256, GEMM_SMEM>>>(
        attnh, wpth, b_p, out, nullptr, 0, MROWS, NST, NX_);
}